// round 11
// baseline (speedup 1.0000x reference)
#include <cuda_runtime.h>
#include <cuda_fp16.h>
#include <math.h>
#include <cstdint>

// Problem shape (fixed by the reference).
#define Bq      4
#define SEQ     2048
#define DMODEL  1024
#define NH      16
#define DH      64
#define ROWS    (Bq * SEQ)      // 8192

#define F32_EPS 1.1920929e-07f

// fp16 scratch: device globals (no cudaMalloc allowed).
__device__ __half g_xh[ROWS * DMODEL];
__device__ __half g_Wqh[DMODEL * DMODEL];
__device__ __half g_Wkh[DMODEL * DMODEL];
__device__ __half g_Wvh[DMODEL * DMODEL];
__device__ __half g_Woh[DMODEL * DMODEL];
__device__ __half g_Qh[ROWS * DMODEL];
__device__ __half g_Kh[ROWS * DMODEL];
__device__ __half g_Vh[ROWS * DMODEL];
__device__ __half g_Oh[ROWS * DMODEL];

// ===========================================================================
// Helpers.
// ===========================================================================
__device__ __forceinline__ uint32_t smem_to_u32(const void* p) {
    uint32_t a;
    asm("{ .reg .u64 t; cvta.to.shared.u64 t, %1; cvt.u32.u64 %0, t; }"
        : "=r"(a) : "l"(p));
    return a;
}
__device__ __forceinline__ void mma_f16(float* c, uint32_t a0, uint32_t a1,
                                        uint32_t a2, uint32_t a3,
                                        uint32_t b0, uint32_t b1) {
    asm volatile(
        "mma.sync.aligned.m16n8k16.row.col.f32.f16.f16.f32 "
        "{%0,%1,%2,%3}, {%4,%5,%6,%7}, {%8,%9}, {%0,%1,%2,%3};"
        : "+f"(c[0]), "+f"(c[1]), "+f"(c[2]), "+f"(c[3])
        : "r"(a0), "r"(a1), "r"(a2), "r"(a3), "r"(b0), "r"(b1));
}
__device__ __forceinline__ void ldsm_x4(uint32_t& r0, uint32_t& r1,
                                        uint32_t& r2, uint32_t& r3, uint32_t a) {
    asm volatile("ldmatrix.sync.aligned.m8n8.x4.shared.b16 {%0,%1,%2,%3}, [%4];"
                 : "=r"(r0), "=r"(r1), "=r"(r2), "=r"(r3) : "r"(a));
}
__device__ __forceinline__ void ldsm_x4_t(uint32_t& r0, uint32_t& r1,
                                          uint32_t& r2, uint32_t& r3, uint32_t a) {
    asm volatile("ldmatrix.sync.aligned.m8n8.x4.trans.shared.b16 {%0,%1,%2,%3}, [%4];"
                 : "=r"(r0), "=r"(r1), "=r"(r2), "=r"(r3) : "r"(a));
}
__device__ __forceinline__ void cp_async16(uint32_t dst, const void* src) {
    asm volatile("cp.async.cg.shared.global [%0], [%1], 16;"
                 :: "r"(dst), "l"(src));
}
#define CP_COMMIT() asm volatile("cp.async.commit_group;" ::: "memory")
#define CP_WAIT(n)  asm volatile("cp.async.wait_group %0;" :: "n"(n) : "memory")

__device__ __forceinline__ uint32_t packh2(float x, float y) {
    __half2 h = __floats2half2_rn(x, y);
    return *(uint32_t*)&h;
}
// 2 exponentials (base 2) on a packed half2 in ONE MUFU op.
__device__ __forceinline__ uint32_t h2ex2(uint32_t x) {
    uint32_t r;
    asm("ex2.approx.f16x2 %0, %1;" : "=r"(r) : "r"(x));
    return r;
}

// ===========================================================================
// Fused fp32 -> fp16 conversion: x (2M float4) then 4 weights (256K each).
// ===========================================================================
#define NX4 (ROWS * DMODEL / 4)      // 2097152
#define NW4 (DMODEL * DMODEL / 4)    // 262144

__global__ void cvt_all(const float4* __restrict__ x,
                        const float4* __restrict__ w0,
                        const float4* __restrict__ w1,
                        const float4* __restrict__ w2,
                        const float4* __restrict__ w3,
                        uint2* __restrict__ dx, uint2* __restrict__ dw0,
                        uint2* __restrict__ dw1, uint2* __restrict__ dw2,
                        uint2* __restrict__ dw3)
{
    int i = blockIdx.x * blockDim.x + threadIdx.x;
    const float4* s;
    uint2* d;
    int idx;
    if (i < NX4) {
        s = x; d = dx; idx = i;
    } else {
        int j = i - NX4;
        int wsel = j >> 18;                 // NW4 = 2^18
        idx = j & (NW4 - 1);
        s = wsel == 0 ? w0 : wsel == 1 ? w1 : wsel == 2 ? w2 : w3;
        d = wsel == 0 ? dw0 : wsel == 1 ? dw1 : wsel == 2 ? dw2 : dw3;
    }
    float4 v = s[idx];
    d[idx] = make_uint2(packh2(v.x, v.y), packh2(v.z, v.w));
}

// ===========================================================================
// fp16 tensor-core GEMM body (NT) — R8-best config:
// CTA 128x128, BK=64, 3-stage cp.async pipeline, 128 threads:
// 4 warps (2M x 2N), warp tile 64x64 = 4 mf x 8 nf of m16n8k16.
// ===========================================================================
#define GBK     64
#define GNCH    (DMODEL / GBK)       // 16
#define GASTR   72                   // halves per smem row (144 B)
#define GMATB   (128 * GASTR * 2)    // 18432 bytes per matrix per stage
#define GSTGB   (2 * GMATB)          // 36864 bytes per stage
#define GSM_BYTES (3 * GSTGB)        // 110592

__device__ __forceinline__ void
gemm_body(__half* gsm, const __half* __restrict__ A, const __half* __restrict__ B,
          void* __restrict__ Cv, const float* __restrict__ w,
          int do_rms, int out_half, int bm, int bn)
{
    const uint32_t sb = smem_to_u32(gsm);
    const int tid  = threadIdx.x;
    const int wid  = tid >> 5;
    const int lane = tid & 31;
    const int g    = lane >> 2;
    const int t    = lane & 3;
    const int warpM = wid >> 1;
    const int warpN = wid & 1;

    const int l15 = lane & 15, lq = lane >> 4;
    const int rbl = lq * 8 + (lane & 7);
    const int cob = ((lane >> 3) & 1) * 8;

    const __half* Ag = A + (size_t)bm * DMODEL;
    const __half* Bg = B + (size_t)bn * DMODEL;

    float acc[4][8][4];
#pragma unroll
    for (int i = 0; i < 4; i++)
#pragma unroll
        for (int j = 0; j < 8; j++)
#pragma unroll
            for (int k = 0; k < 4; k++) acc[i][j][k] = 0.f;

    auto load_stage = [&](int chunk, int st) {
        const uint32_t abase = sb + (uint32_t)st * GSTGB;
        const uint32_t bbase = abase + GMATB;
#pragma unroll
        for (int i = 0; i < 8; i++) {
            const int idx = tid + i * 128;
            const int row = idx >> 3;
            const int c8  = idx & 7;
            const uint32_t so = (uint32_t)(row * GASTR + c8 * 8) * 2u;
            const size_t go = (size_t)row * DMODEL + chunk * GBK + c8 * 8;
            cp_async16(abase + so, Ag + go);
            cp_async16(bbase + so, Bg + go);
        }
    };

    load_stage(0, 0); CP_COMMIT();
    load_stage(1, 1); CP_COMMIT();

    for (int i = 0; i < GNCH; i++) {
        const int st = i % 3;
        if (i == GNCH - 1) { CP_WAIT(0); } else { CP_WAIT(1); }
        __syncthreads();
        if (i + 2 < GNCH) { load_stage(i + 2, (i + 2) % 3); CP_COMMIT(); }

        const uint32_t abase = sb + (uint32_t)st * GSTGB;
        const uint32_t bbase = abase + GMATB;
#pragma unroll
        for (int ks = 0; ks < 4; ks++) {
            uint32_t a[4][4];
#pragma unroll
            for (int mf = 0; mf < 4; mf++)
                ldsm_x4(a[mf][0], a[mf][1], a[mf][2], a[mf][3],
                        abase + (uint32_t)((warpM * 64 + mf * 16 + l15) * GASTR
                                           + ks * 16 + lq * 8) * 2u);
#pragma unroll
            for (int nfp = 0; nfp < 4; nfp++) {
                uint32_t b0, b1, b2, b3;
                ldsm_x4(b0, b1, b2, b3,
                        bbase + (uint32_t)((warpN * 64 + nfp * 16 + rbl) * GASTR
                                           + ks * 16 + cob) * 2u);
#pragma unroll
                for (int mf = 0; mf < 4; mf++) {
                    mma_f16(acc[mf][2 * nfp],     a[mf][0], a[mf][1], a[mf][2], a[mf][3], b0, b1);
                    mma_f16(acc[mf][2 * nfp + 1], a[mf][0], a[mf][1], a[mf][2], a[mf][3], b2, b3);
                }
            }
        }
    }

    // ---------------- epilogue --------------------------------------------
#pragma unroll
    for (int mf = 0; mf < 4; mf++) {
        if (do_rms) {
            float ssl = 0.f, ssh = 0.f;
#pragma unroll
            for (int nf = 0; nf < 8; nf++) {
                ssl += acc[mf][nf][0] * acc[mf][nf][0]
                     + acc[mf][nf][1] * acc[mf][nf][1];
                ssh += acc[mf][nf][2] * acc[mf][nf][2]
                     + acc[mf][nf][3] * acc[mf][nf][3];
            }
            ssl += __shfl_xor_sync(0xFFFFFFFFu, ssl, 1);
            ssl += __shfl_xor_sync(0xFFFFFFFFu, ssl, 2);
            ssh += __shfl_xor_sync(0xFFFFFFFFu, ssh, 1);
            ssh += __shfl_xor_sync(0xFFFFFFFFu, ssh, 2);
            const float rl = rsqrtf(ssl * (1.0f / 64.0f) + F32_EPS);
            const float rh = rsqrtf(ssh * (1.0f / 64.0f) + F32_EPS);
#pragma unroll
            for (int nf = 0; nf < 8; nf++) {
                const int hc = nf * 8 + 2 * t;
                const float w0 = w[hc], w1 = w[hc + 1];
                acc[mf][nf][0] *= rl * w0;
                acc[mf][nf][1] *= rl * w1;
                acc[mf][nf][2] *= rh * w0;
                acc[mf][nf][3] *= rh * w1;
            }
        }
        const int r0 = bm + warpM * 64 + mf * 16 + g;
        const int cc = bn + warpN * 64 + 2 * t;
        if (out_half) {
            __half* C = (__half*)Cv;
            uint32_t* c0 = (uint32_t*)(C + (size_t)r0 * DMODEL + cc);
            uint32_t* c1 = (uint32_t*)(C + (size_t)(r0 + 8) * DMODEL + cc);
#pragma unroll
            for (int nf = 0; nf < 8; nf++) {
                c0[nf * 4] = packh2(acc[mf][nf][0], acc[mf][nf][1]);
                c1[nf * 4] = packh2(acc[mf][nf][2], acc[mf][nf][3]);
            }
        } else {
            float* C = (float*)Cv;
            float* c0 = C + (size_t)r0 * DMODEL + cc;
            float* c1 = C + (size_t)(r0 + 8) * DMODEL + cc;
#pragma unroll
            for (int nf = 0; nf < 8; nf++) {
                *(float2*)(c0 + nf * 8) = make_float2(acc[mf][nf][0], acc[mf][nf][1]);
                *(float2*)(c1 + nf * 8) = make_float2(acc[mf][nf][2], acc[mf][nf][3]);
            }
        }
    }
}

// Fused QKV projection (R8 config): grid.x = 24 (matrix = x/8, col tile = x%8).
__global__ void __launch_bounds__(128, 2)
gemm_qkv(const __half* __restrict__ A,
         const __half* __restrict__ Bqm, const __half* __restrict__ Bkm,
         const __half* __restrict__ Bvm,
         __half* __restrict__ Cq, __half* __restrict__ Ck, __half* __restrict__ Cv_,
         const float* __restrict__ qn, const float* __restrict__ kn)
{
    extern __shared__ __half gsm[];
    const int m = blockIdx.x >> 3;
    const int bn = (blockIdx.x & 7) * 128;
    const __half* B = m == 0 ? Bqm : m == 1 ? Bkm : Bvm;
    __half* C = m == 0 ? Cq : m == 1 ? Ck : Cv_;
    const float* w = m == 0 ? qn : m == 1 ? kn : nullptr;
    gemm_body(gsm, A, B, C, w, m < 2 ? 1 : 0, 1, blockIdx.y * 128, bn);
}

// Single GEMM (output projection), fp32 out.
__global__ void __launch_bounds__(128, 2)
gemm_f16(const __half* __restrict__ A, const __half* __restrict__ B,
         void* __restrict__ Cv, const float* __restrict__ w,
         int do_rms, int out_half)
{
    extern __shared__ __half gsm[];
    gemm_body(gsm, A, B, Cv, w, do_rms, out_half,
              blockIdx.y * 128, blockIdx.x * 128);
}

// ===========================================================================
// fp16 flash attention — 256 q-rows per CTA (8 warps x 32 rows, 256 threads,
// 1 CTA/SM): ONE staged K/V tile per SM feeds 8 warps (halves smem writes
// per tile-epoch vs two 128-row CTAs). Per-warp math identical to R8.
// No online softmax (|s|<=8 bound), f16x2 exponent, 3-buffer KV ring.
// ===========================================================================
#define HSTR 72                       // halves per smem row (144 B)
#define FA_TILEH (64 * HSTR)          // 4608 halves per KV buffer
#define FA_NT (SEQ / 64)              // 32
#define FA_BYTES (6 * FA_TILEH * 2)   // 55296 B (K0K1K2 V0V1V2)
#define FA_QROWS 256

__global__ void __launch_bounds__(256, 1)
flash_attn_f16(const __half* __restrict__ Q, const __half* __restrict__ K,
               const __half* __restrict__ V, __half* __restrict__ O)
{
    extern __shared__ __half fs[];
    const uint32_t sb = smem_to_u32(fs);
    const int tid  = threadIdx.x;
    const int wid  = tid >> 5;          // 0..7
    const int lane = tid & 31;
    const int g    = lane >> 2;
    const int t    = lane & 3;
    const int bh = blockIdx.y;
    const int b  = bh >> 4;
    const int h  = bh & 15;
    const size_t rowbase = (size_t)b * SEQ;
    const int qm0 = blockIdx.x * FA_QROWS;
    const int m0  = wid * 32;

    const int l15 = lane & 15, lq = lane >> 4;
    const int rbl = lq * 8 + (lane & 7);             // K ldmatrix row pattern
    const int cob = ((lane >> 3) & 1) * 8;           // K col offset
    const int rv  = ((lane >> 3) & 1) * 8 + (lane & 7);  // V trans row pattern
    const int cv  = lq * 8;                          // V trans col offset

    // ---- stage Q (256 x 64 halves) across the first 4 KV buffers ----
    {
        const __half* Qg = Q + (rowbase + qm0) * DMODEL + h * DH;
#pragma unroll
        for (int i = 0; i < 8; i++) {
            const int idx = tid + i * 256;          // 0..2047
            const int row = idx >> 3, c8 = idx & 7; // row 0..255
            cp_async16(sb + (uint32_t)(row * HSTR + c8 * 8) * 2u,
                       Qg + (size_t)row * DMODEL + c8 * 8);
        }
        CP_COMMIT(); CP_WAIT(0);
        __syncthreads();
    }
    uint32_t qf[2][4][4];
    // scale = 1/sqrt(64) * log2(e): ex2(s) == exp(q.k / 8)
    const __half2 qsc = __float2half2_rn(0.125f * 1.4426950408889634f);
#pragma unroll
    for (int mf = 0; mf < 2; mf++)
#pragma unroll
        for (int ks = 0; ks < 4; ks++) {
            ldsm_x4(qf[mf][ks][0], qf[mf][ks][1], qf[mf][ks][2], qf[mf][ks][3],
                    sb + (uint32_t)((m0 + mf * 16 + l15) * HSTR
                                    + ks * 16 + lq * 8) * 2u);
#pragma unroll
            for (int j = 0; j < 4; j++) {
                __half2* hp = (__half2*)&qf[mf][ks][j];
                *hp = __hmul2(*hp, qsc);
            }
        }
    __syncthreads();   // Q staging region about to be reused by KV buffers

    float acc_o[2][8][4];
#pragma unroll
    for (int i = 0; i < 2; i++)
#pragma unroll
        for (int j = 0; j < 8; j++)
#pragma unroll
            for (int k = 0; k < 4; k++) acc_o[i][j][k] = 0.f;
    float lr[2][2] = {{0.f, 0.f}, {0.f, 0.f}};

    auto load_kv = [&](int tile, int buf) {
        const __half* Kg = K + (rowbase + tile * 64) * DMODEL + h * DH;
        const __half* Vg = V + (rowbase + tile * 64) * DMODEL + h * DH;
        const uint32_t kb = sb + (uint32_t)(buf * FA_TILEH) * 2u;
        const uint32_t vb = sb + (uint32_t)((3 + buf) * FA_TILEH) * 2u;
#pragma unroll
        for (int i = 0; i < 2; i++) {
            const int idx = tid + i * 256;          // 0..511
            const int row = idx >> 3, c8 = idx & 7;
            const uint32_t so = (uint32_t)(row * HSTR + c8 * 8) * 2u;
            const size_t go = (size_t)row * DMODEL + c8 * 8;
            cp_async16(kb + so, Kg + go);
            cp_async16(vb + so, Vg + go);
        }
    };

    load_kv(0, 0); CP_COMMIT();
    load_kv(1, 1); CP_COMMIT();

    for (int it = 0; it < FA_NT; it++) {
        const int buf = it % 3;
        if (it + 1 < FA_NT) { CP_WAIT(1); } else { CP_WAIT(0); }
        __syncthreads();     // tile `it` visible; buffer (it-1)%3 free to refill
        if (it + 2 < FA_NT) { load_kv(it + 2, (it + 2) % 3); CP_COMMIT(); }

        // ---- S = Q * K^T (log2 units) ----
        float s[2][8][4];
#pragma unroll
        for (int i = 0; i < 2; i++)
#pragma unroll
            for (int j = 0; j < 8; j++)
#pragma unroll
                for (int k = 0; k < 4; k++) s[i][j][k] = 0.f;

        const uint32_t kbase = sb + (uint32_t)(buf * FA_TILEH) * 2u;
#pragma unroll
        for (int ks = 0; ks < 4; ks++) {
#pragma unroll
            for (int nfp = 0; nfp < 4; nfp++) {
                uint32_t b0, b1, b2, b3;
                ldsm_x4(b0, b1, b2, b3,
                        kbase + (uint32_t)((nfp * 16 + rbl) * HSTR
                                           + ks * 16 + cob) * 2u);
#pragma unroll
                for (int mf = 0; mf < 2; mf++) {
                    mma_f16(s[mf][2 * nfp],     qf[mf][ks][0], qf[mf][ks][1],
                            qf[mf][ks][2], qf[mf][ks][3], b0, b1);
                    mma_f16(s[mf][2 * nfp + 1], qf[mf][ks][0], qf[mf][ks][1],
                            qf[mf][ks][2], qf[mf][ks][3], b2, b3);
                }
            }
        }

        // ---- p = 2^s via f16x2 MUFU; half2 row-sum trees; p IS the A-frag ----
        uint32_t ph[2][8][2];
#pragma unroll
        for (int mf = 0; mf < 2; mf++) {
            __half2 sum0 = __float2half2_rn(0.f);
            __half2 sum1 = __float2half2_rn(0.f);
#pragma unroll
            for (int nf = 0; nf < 8; nf++) {
                ph[mf][nf][0] = h2ex2(packh2(s[mf][nf][0], s[mf][nf][1]));
                ph[mf][nf][1] = h2ex2(packh2(s[mf][nf][2], s[mf][nf][3]));
                sum0 = __hadd2(sum0, *(__half2*)&ph[mf][nf][0]);
                sum1 = __hadd2(sum1, *(__half2*)&ph[mf][nf][1]);
            }
            float2 f0 = __half22float2(sum0);
            float2 f1 = __half22float2(sum1);
            lr[mf][0] += f0.x + f0.y;
            lr[mf][1] += f1.x + f1.y;
        }

        // ---- O += P * V ----
        const uint32_t vbase = sb + (uint32_t)((3 + buf) * FA_TILEH) * 2u;
#pragma unroll
        for (int ks = 0; ks < 4; ks++) {
#pragma unroll
            for (int nfp = 0; nfp < 4; nfp++) {
                uint32_t b0, b1, b2, b3;
                ldsm_x4_t(b0, b1, b2, b3,
                          vbase + (uint32_t)((ks * 16 + rv) * HSTR
                                             + nfp * 16 + cv) * 2u);
#pragma unroll
                for (int mf = 0; mf < 2; mf++) {
                    mma_f16(acc_o[mf][2 * nfp],     ph[mf][2 * ks][0], ph[mf][2 * ks][1],
                            ph[mf][2 * ks + 1][0], ph[mf][2 * ks + 1][1], b0, b1);
                    mma_f16(acc_o[mf][2 * nfp + 1], ph[mf][2 * ks][0], ph[mf][2 * ks][1],
                            ph[mf][2 * ks + 1][0], ph[mf][2 * ks + 1][1], b2, b3);
                }
            }
        }
    }

    // ---- epilogue: reduce l across quad once, O / l -> fp16 global ----
#pragma unroll
    for (int mf = 0; mf < 2; mf++) {
        float l0 = lr[mf][0], l1 = lr[mf][1];
        l0 += __shfl_xor_sync(0xFFFFFFFFu, l0, 1);
        l0 += __shfl_xor_sync(0xFFFFFFFFu, l0, 2);
        l1 += __shfl_xor_sync(0xFFFFFFFFu, l1, 1);
        l1 += __shfl_xor_sync(0xFFFFFFFFu, l1, 2);
        const float inv0 = 1.f / l0;
        const float inv1 = 1.f / l1;
        __half* o0 = O + (rowbase + qm0 + m0 + mf * 16 + g) * (size_t)DMODEL
                       + h * DH + 2 * t;
        __half* o1 = o0 + 8 * DMODEL;
#pragma unroll
        for (int nf = 0; nf < 8; nf++) {
            *(uint32_t*)(o0 + nf * 8) =
                packh2(acc_o[mf][nf][0] * inv0, acc_o[mf][nf][1] * inv0);
            *(uint32_t*)(o1 + nf * 8) =
                packh2(acc_o[mf][nf][2] * inv1, acc_o[mf][nf][3] * inv1);
        }
    }
}

// ---------------------------------------------------------------------------
// Launch.
// ---------------------------------------------------------------------------
extern "C" void kernel_launch(void* const* d_in, const int* in_sizes, int n_in,
                              void* d_out, int out_size)
{
    const float* x  = (const float*)d_in[0];
    const float* Wq = (const float*)d_in[1];
    const float* Wk = (const float*)d_in[2];
    const float* Wv = (const float*)d_in[3];
    const float* Wo = (const float*)d_in[4];
    const float* qn = (const float*)d_in[5];
    const float* kn = (const float*)d_in[6];
    float* out = (float*)d_out;

    __half *xh, *wqh, *wkh, *wvh, *woh, *Qh, *Kh, *Vh, *Oh;
    cudaGetSymbolAddress((void**)&xh,  g_xh);
    cudaGetSymbolAddress((void**)&wqh, g_Wqh);
    cudaGetSymbolAddress((void**)&wkh, g_Wkh);
    cudaGetSymbolAddress((void**)&wvh, g_Wvh);
    cudaGetSymbolAddress((void**)&woh, g_Woh);
    cudaGetSymbolAddress((void**)&Qh,  g_Qh);
    cudaGetSymbolAddress((void**)&Kh,  g_Kh);
    cudaGetSymbolAddress((void**)&Vh,  g_Vh);
    cudaGetSymbolAddress((void**)&Oh,  g_Oh);

    cudaFuncSetAttribute(gemm_f16,
                         cudaFuncAttributeMaxDynamicSharedMemorySize, GSM_BYTES);
    cudaFuncSetAttribute(gemm_qkv,
                         cudaFuncAttributeMaxDynamicSharedMemorySize, GSM_BYTES);
    cudaFuncSetAttribute(flash_attn_f16,
                         cudaFuncAttributeMaxDynamicSharedMemorySize, FA_BYTES);

    // fused fp32 -> fp16 conversion (x + 4 weights)
    const int ntot = NX4 + 4 * NW4;             // 3145728
    cvt_all<<<ntot / 256, 256>>>((const float4*)x, (const float4*)Wq,
                                 (const float4*)Wk, (const float4*)Wv,
                                 (const float4*)Wo,
                                 (uint2*)xh, (uint2*)wqh, (uint2*)wkh,
                                 (uint2*)wvh, (uint2*)woh);

    // fused QKV projection (R8 config)
    gemm_qkv<<<dim3(24, ROWS / 128), 128, GSM_BYTES>>>(
        xh, wqh, wkh, wvh, Qh, Kh, Vh, qn, kn);

    flash_attn_f16<<<dim3(SEQ / FA_QROWS, Bq * NH), 256, FA_BYTES>>>(
        Qh, Kh, Vh, Oh);

    gemm_f16<<<dim3(DMODEL / 128, ROWS / 128), 128, GSM_BYTES>>>(
        Oh, woh, out, nullptr, 0, 0);
}

// round 12
// speedup vs baseline: 1.0889x; 1.0889x over previous
#include <cuda_runtime.h>
#include <cuda_fp16.h>
#include <math.h>
#include <cstdint>

// Problem shape (fixed by the reference).
#define Bq      4
#define SEQ     2048
#define DMODEL  1024
#define NH      16
#define DH      64
#define ROWS    (Bq * SEQ)      // 8192

#define F32_EPS 1.1920929e-07f

// fp16 scratch: device globals (no cudaMalloc allowed).
__device__ __half g_xh[ROWS * DMODEL];
__device__ __half g_Wqh[DMODEL * DMODEL];
__device__ __half g_Wkh[DMODEL * DMODEL];
__device__ __half g_Wvh[DMODEL * DMODEL];
__device__ __half g_Woh[DMODEL * DMODEL];
__device__ __half g_Qh[ROWS * DMODEL];
__device__ __half g_Kh[ROWS * DMODEL];
__device__ __half g_Vh[ROWS * DMODEL];
__device__ __half g_Oh[ROWS * DMODEL];

// ===========================================================================
// Helpers.
// ===========================================================================
__device__ __forceinline__ uint32_t smem_to_u32(const void* p) {
    uint32_t a;
    asm("{ .reg .u64 t; cvta.to.shared.u64 t, %1; cvt.u32.u64 %0, t; }"
        : "=r"(a) : "l"(p));
    return a;
}
__device__ __forceinline__ void mma_f16(float* c, uint32_t a0, uint32_t a1,
                                        uint32_t a2, uint32_t a3,
                                        uint32_t b0, uint32_t b1) {
    asm volatile(
        "mma.sync.aligned.m16n8k16.row.col.f32.f16.f16.f32 "
        "{%0,%1,%2,%3}, {%4,%5,%6,%7}, {%8,%9}, {%0,%1,%2,%3};"
        : "+f"(c[0]), "+f"(c[1]), "+f"(c[2]), "+f"(c[3])
        : "r"(a0), "r"(a1), "r"(a2), "r"(a3), "r"(b0), "r"(b1));
}
__device__ __forceinline__ void ldsm_x4(uint32_t& r0, uint32_t& r1,
                                        uint32_t& r2, uint32_t& r3, uint32_t a) {
    asm volatile("ldmatrix.sync.aligned.m8n8.x4.shared.b16 {%0,%1,%2,%3}, [%4];"
                 : "=r"(r0), "=r"(r1), "=r"(r2), "=r"(r3) : "r"(a));
}
__device__ __forceinline__ void ldsm_x4_t(uint32_t& r0, uint32_t& r1,
                                          uint32_t& r2, uint32_t& r3, uint32_t a) {
    asm volatile("ldmatrix.sync.aligned.m8n8.x4.trans.shared.b16 {%0,%1,%2,%3}, [%4];"
                 : "=r"(r0), "=r"(r1), "=r"(r2), "=r"(r3) : "r"(a));
}
__device__ __forceinline__ void cp_async16(uint32_t dst, const void* src) {
    asm volatile("cp.async.cg.shared.global [%0], [%1], 16;"
                 :: "r"(dst), "l"(src));
}
#define CP_COMMIT() asm volatile("cp.async.commit_group;" ::: "memory")
#define CP_WAIT(n)  asm volatile("cp.async.wait_group %0;" :: "n"(n) : "memory")

__device__ __forceinline__ uint32_t packh2(float x, float y) {
    __half2 h = __floats2half2_rn(x, y);
    return *(uint32_t*)&h;
}
// 2 exponentials (base 2) on a packed half2 in ONE MUFU op.
__device__ __forceinline__ uint32_t h2ex2(uint32_t x) {
    uint32_t r;
    asm("ex2.approx.f16x2 %0, %1;" : "=r"(r) : "r"(x));
    return r;
}

// ===========================================================================
// fp32 -> fp16 conversion, MLP=4: each thread issues 4 coalesced float4
// loads per iteration (B300: MLP>=4 fully hides DRAM latency).
// One kernel converts x + the 4 weight matrices via a per-block region select.
// ===========================================================================
#define NX4 (ROWS * DMODEL / 4)      // 2097152 float4s in x
#define NW4 (DMODEL * DMODEL / 4)    // 262144 float4s per weight
#define NTOT4 (NX4 + 4 * NW4)        // 3145728
#define CVT_TPB 256
#define CVT_PER_THREAD 4
#define CVT_BLOCKS (NTOT4 / (CVT_TPB * CVT_PER_THREAD))   // 3072

__global__ void __launch_bounds__(CVT_TPB)
cvt_all(const float4* __restrict__ x,
        const float4* __restrict__ w0, const float4* __restrict__ w1,
        const float4* __restrict__ w2, const float4* __restrict__ w3,
        uint2* __restrict__ dx, uint2* __restrict__ dw0,
        uint2* __restrict__ dw1, uint2* __restrict__ dw2,
        uint2* __restrict__ dw3)
{
    // Block-contiguous region: block b owns [b*1024, (b+1)*1024) float4s.
    const int base = blockIdx.x * (CVT_TPB * CVT_PER_THREAD);
    const float4* s;
    uint2* d;
    int rbase;
    if (base < NX4) {                       // whole block inside x (NX4 % 1024 == 0)
        s = x; d = dx; rbase = base;
    } else {
        int j = base - NX4;
        int wsel = j >> 18;                 // NW4 = 2^18, block never straddles
        rbase = j & (NW4 - 1);
        s = wsel == 0 ? w0 : wsel == 1 ? w1 : wsel == 2 ? w2 : w3;
        d = wsel == 0 ? dw0 : wsel == 1 ? dw1 : wsel == 2 ? dw2 : dw3;
    }
    float4 v[CVT_PER_THREAD];
#pragma unroll
    for (int i = 0; i < CVT_PER_THREAD; i++)
        v[i] = s[rbase + threadIdx.x + i * CVT_TPB];    // 4 loads in flight
#pragma unroll
    for (int i = 0; i < CVT_PER_THREAD; i++)
        d[rbase + threadIdx.x + i * CVT_TPB] =
            make_uint2(packh2(v[i].x, v[i].y), packh2(v[i].z, v[i].w));
}

// ===========================================================================
// fp16 tensor-core GEMM body (NT) — R8-best config (byte-identical):
// CTA 128x128, BK=64, 3-stage cp.async pipeline, 128 threads:
// 4 warps (2M x 2N), warp tile 64x64 = 4 mf x 8 nf of m16n8k16.
// ===========================================================================
#define GBK     64
#define GNCH    (DMODEL / GBK)       // 16
#define GASTR   72                   // halves per smem row (144 B)
#define GMATB   (128 * GASTR * 2)    // 18432 bytes per matrix per stage
#define GSTGB   (2 * GMATB)          // 36864 bytes per stage
#define GSM_BYTES (3 * GSTGB)        // 110592

__device__ __forceinline__ void
gemm_body(__half* gsm, const __half* __restrict__ A, const __half* __restrict__ B,
          void* __restrict__ Cv, const float* __restrict__ w,
          int do_rms, int out_half, int bm, int bn)
{
    const uint32_t sb = smem_to_u32(gsm);
    const int tid  = threadIdx.x;
    const int wid  = tid >> 5;
    const int lane = tid & 31;
    const int g    = lane >> 2;
    const int t    = lane & 3;
    const int warpM = wid >> 1;
    const int warpN = wid & 1;

    const int l15 = lane & 15, lq = lane >> 4;
    const int rbl = lq * 8 + (lane & 7);
    const int cob = ((lane >> 3) & 1) * 8;

    const __half* Ag = A + (size_t)bm * DMODEL;
    const __half* Bg = B + (size_t)bn * DMODEL;

    float acc[4][8][4];
#pragma unroll
    for (int i = 0; i < 4; i++)
#pragma unroll
        for (int j = 0; j < 8; j++)
#pragma unroll
            for (int k = 0; k < 4; k++) acc[i][j][k] = 0.f;

    auto load_stage = [&](int chunk, int st) {
        const uint32_t abase = sb + (uint32_t)st * GSTGB;
        const uint32_t bbase = abase + GMATB;
#pragma unroll
        for (int i = 0; i < 8; i++) {
            const int idx = tid + i * 128;
            const int row = idx >> 3;
            const int c8  = idx & 7;
            const uint32_t so = (uint32_t)(row * GASTR + c8 * 8) * 2u;
            const size_t go = (size_t)row * DMODEL + chunk * GBK + c8 * 8;
            cp_async16(abase + so, Ag + go);
            cp_async16(bbase + so, Bg + go);
        }
    };

    load_stage(0, 0); CP_COMMIT();
    load_stage(1, 1); CP_COMMIT();

    for (int i = 0; i < GNCH; i++) {
        const int st = i % 3;
        if (i == GNCH - 1) { CP_WAIT(0); } else { CP_WAIT(1); }
        __syncthreads();
        if (i + 2 < GNCH) { load_stage(i + 2, (i + 2) % 3); CP_COMMIT(); }

        const uint32_t abase = sb + (uint32_t)st * GSTGB;
        const uint32_t bbase = abase + GMATB;
#pragma unroll
        for (int ks = 0; ks < 4; ks++) {
            uint32_t a[4][4];
#pragma unroll
            for (int mf = 0; mf < 4; mf++)
                ldsm_x4(a[mf][0], a[mf][1], a[mf][2], a[mf][3],
                        abase + (uint32_t)((warpM * 64 + mf * 16 + l15) * GASTR
                                           + ks * 16 + lq * 8) * 2u);
#pragma unroll
            for (int nfp = 0; nfp < 4; nfp++) {
                uint32_t b0, b1, b2, b3;
                ldsm_x4(b0, b1, b2, b3,
                        bbase + (uint32_t)((warpN * 64 + nfp * 16 + rbl) * GASTR
                                           + ks * 16 + cob) * 2u);
#pragma unroll
                for (int mf = 0; mf < 4; mf++) {
                    mma_f16(acc[mf][2 * nfp],     a[mf][0], a[mf][1], a[mf][2], a[mf][3], b0, b1);
                    mma_f16(acc[mf][2 * nfp + 1], a[mf][0], a[mf][1], a[mf][2], a[mf][3], b2, b3);
                }
            }
        }
    }

    // ---------------- epilogue --------------------------------------------
#pragma unroll
    for (int mf = 0; mf < 4; mf++) {
        if (do_rms) {
            float ssl = 0.f, ssh = 0.f;
#pragma unroll
            for (int nf = 0; nf < 8; nf++) {
                ssl += acc[mf][nf][0] * acc[mf][nf][0]
                     + acc[mf][nf][1] * acc[mf][nf][1];
                ssh += acc[mf][nf][2] * acc[mf][nf][2]
                     + acc[mf][nf][3] * acc[mf][nf][3];
            }
            ssl += __shfl_xor_sync(0xFFFFFFFFu, ssl, 1);
            ssl += __shfl_xor_sync(0xFFFFFFFFu, ssl, 2);
            ssh += __shfl_xor_sync(0xFFFFFFFFu, ssh, 1);
            ssh += __shfl_xor_sync(0xFFFFFFFFu, ssh, 2);
            const float rl = rsqrtf(ssl * (1.0f / 64.0f) + F32_EPS);
            const float rh = rsqrtf(ssh * (1.0f / 64.0f) + F32_EPS);
#pragma unroll
            for (int nf = 0; nf < 8; nf++) {
                const int hc = nf * 8 + 2 * t;
                const float w0 = w[hc], w1 = w[hc + 1];
                acc[mf][nf][0] *= rl * w0;
                acc[mf][nf][1] *= rl * w1;
                acc[mf][nf][2] *= rh * w0;
                acc[mf][nf][3] *= rh * w1;
            }
        }
        const int r0 = bm + warpM * 64 + mf * 16 + g;
        const int cc = bn + warpN * 64 + 2 * t;
        if (out_half) {
            __half* C = (__half*)Cv;
            uint32_t* c0 = (uint32_t*)(C + (size_t)r0 * DMODEL + cc);
            uint32_t* c1 = (uint32_t*)(C + (size_t)(r0 + 8) * DMODEL + cc);
#pragma unroll
            for (int nf = 0; nf < 8; nf++) {
                c0[nf * 4] = packh2(acc[mf][nf][0], acc[mf][nf][1]);
                c1[nf * 4] = packh2(acc[mf][nf][2], acc[mf][nf][3]);
            }
        } else {
            float* C = (float*)Cv;
            float* c0 = C + (size_t)r0 * DMODEL + cc;
            float* c1 = C + (size_t)(r0 + 8) * DMODEL + cc;
#pragma unroll
            for (int nf = 0; nf < 8; nf++) {
                *(float2*)(c0 + nf * 8) = make_float2(acc[mf][nf][0], acc[mf][nf][1]);
                *(float2*)(c1 + nf * 8) = make_float2(acc[mf][nf][2], acc[mf][nf][3]);
            }
        }
    }
}

// Fused QKV projection (R8 config): grid.x = 24 (matrix = x/8, col tile = x%8).
__global__ void __launch_bounds__(128, 2)
gemm_qkv(const __half* __restrict__ A,
         const __half* __restrict__ Bqm, const __half* __restrict__ Bkm,
         const __half* __restrict__ Bvm,
         __half* __restrict__ Cq, __half* __restrict__ Ck, __half* __restrict__ Cv_,
         const float* __restrict__ qn, const float* __restrict__ kn)
{
    extern __shared__ __half gsm[];
    const int m = blockIdx.x >> 3;
    const int bn = (blockIdx.x & 7) * 128;
    const __half* B = m == 0 ? Bqm : m == 1 ? Bkm : Bvm;
    __half* C = m == 0 ? Cq : m == 1 ? Ck : Cv_;
    const float* w = m == 0 ? qn : m == 1 ? kn : nullptr;
    gemm_body(gsm, A, B, C, w, m < 2 ? 1 : 0, 1, blockIdx.y * 128, bn);
}

// Single GEMM (output projection), fp32 out.
__global__ void __launch_bounds__(128, 2)
gemm_f16(const __half* __restrict__ A, const __half* __restrict__ B,
         void* __restrict__ Cv, const float* __restrict__ w,
         int do_rms, int out_half)
{
    extern __shared__ __half gsm[];
    gemm_body(gsm, A, B, Cv, w, do_rms, out_half,
              blockIdx.y * 128, blockIdx.x * 128);
}

// ===========================================================================
// fp16 flash attention — R8 config (byte-identical): 128 threads, 4 warps x
// 32 q-rows, 2 CTAs/SM; no online softmax (|s|<=8), f16x2 exponent,
// 3-buffer KV ring (one __syncthreads per tile).
// ===========================================================================
#define HSTR 72                       // halves per smem row (144 B)
#define FA_TILEH (64 * HSTR)          // 4608 halves per KV buffer
#define FA_NT (SEQ / 64)              // 32
#define FA_BYTES (6 * FA_TILEH * 2)   // 55296 B (K0K1K2 V0V1V2)

__global__ void __launch_bounds__(128, 2)
flash_attn_f16(const __half* __restrict__ Q, const __half* __restrict__ K,
               const __half* __restrict__ V, __half* __restrict__ O)
{
    extern __shared__ __half fs[];
    const uint32_t sb = smem_to_u32(fs);
    const int tid  = threadIdx.x;
    const int wid  = tid >> 5;
    const int lane = tid & 31;
    const int g    = lane >> 2;
    const int t    = lane & 3;
    const int bh = blockIdx.y;
    const int b  = bh >> 4;
    const int h  = bh & 15;
    const size_t rowbase = (size_t)b * SEQ;
    const int qm0 = blockIdx.x * 128;
    const int m0  = wid * 32;

    const int l15 = lane & 15, lq = lane >> 4;
    const int rbl = lq * 8 + (lane & 7);             // K ldmatrix row pattern
    const int cob = ((lane >> 3) & 1) * 8;           // K col offset
    const int rv  = ((lane >> 3) & 1) * 8 + (lane & 7);  // V trans row pattern
    const int cv  = lq * 8;                          // V trans col offset

    // ---- stage Q (128 x 64 halves), extract frags ----
    {
        const __half* Qg = Q + (rowbase + qm0) * DMODEL + h * DH;
#pragma unroll
        for (int i = 0; i < 8; i++) {
            const int idx = tid + i * 128;
            const int row = idx >> 3, c8 = idx & 7;
            cp_async16(sb + (uint32_t)(row * HSTR + c8 * 8) * 2u,
                       Qg + (size_t)row * DMODEL + c8 * 8);
        }
        CP_COMMIT(); CP_WAIT(0);
        __syncthreads();
    }
    uint32_t qf[2][4][4];
    // scale = 1/sqrt(64) * log2(e): ex2(s) == exp(q.k / 8)
    const __half2 qsc = __float2half2_rn(0.125f * 1.4426950408889634f);
#pragma unroll
    for (int mf = 0; mf < 2; mf++)
#pragma unroll
        for (int ks = 0; ks < 4; ks++) {
            ldsm_x4(qf[mf][ks][0], qf[mf][ks][1], qf[mf][ks][2], qf[mf][ks][3],
                    sb + (uint32_t)((m0 + mf * 16 + l15) * HSTR
                                    + ks * 16 + lq * 8) * 2u);
#pragma unroll
            for (int j = 0; j < 4; j++) {
                __half2* hp = (__half2*)&qf[mf][ks][j];
                *hp = __hmul2(*hp, qsc);
            }
        }
    __syncthreads();   // Q staging region about to be reused by KV buffers

    float acc_o[2][8][4];
#pragma unroll
    for (int i = 0; i < 2; i++)
#pragma unroll
        for (int j = 0; j < 8; j++)
#pragma unroll
            for (int k = 0; k < 4; k++) acc_o[i][j][k] = 0.f;
    float lr[2][2] = {{0.f, 0.f}, {0.f, 0.f}};

    auto load_kv = [&](int tile, int buf) {
        const __half* Kg = K + (rowbase + tile * 64) * DMODEL + h * DH;
        const __half* Vg = V + (rowbase + tile * 64) * DMODEL + h * DH;
        const uint32_t kb = sb + (uint32_t)(buf * FA_TILEH) * 2u;
        const uint32_t vb = sb + (uint32_t)((3 + buf) * FA_TILEH) * 2u;
#pragma unroll
        for (int i = 0; i < 4; i++) {
            const int idx = tid + i * 128;
            const int row = idx >> 3, c8 = idx & 7;
            const uint32_t so = (uint32_t)(row * HSTR + c8 * 8) * 2u;
            const size_t go = (size_t)row * DMODEL + c8 * 8;
            cp_async16(kb + so, Kg + go);
            cp_async16(vb + so, Vg + go);
        }
    };

    load_kv(0, 0); CP_COMMIT();
    load_kv(1, 1); CP_COMMIT();

    for (int it = 0; it < FA_NT; it++) {
        const int buf = it % 3;
        if (it + 1 < FA_NT) { CP_WAIT(1); } else { CP_WAIT(0); }
        __syncthreads();     // tile `it` visible; buffer (it-1)%3 free to refill
        if (it + 2 < FA_NT) { load_kv(it + 2, (it + 2) % 3); CP_COMMIT(); }

        // ---- S = Q * K^T (log2 units) ----
        float s[2][8][4];
#pragma unroll
        for (int i = 0; i < 2; i++)
#pragma unroll
            for (int j = 0; j < 8; j++)
#pragma unroll
                for (int k = 0; k < 4; k++) s[i][j][k] = 0.f;

        const uint32_t kbase = sb + (uint32_t)(buf * FA_TILEH) * 2u;
#pragma unroll
        for (int ks = 0; ks < 4; ks++) {
#pragma unroll
            for (int nfp = 0; nfp < 4; nfp++) {
                uint32_t b0, b1, b2, b3;
                ldsm_x4(b0, b1, b2, b3,
                        kbase + (uint32_t)((nfp * 16 + rbl) * HSTR
                                           + ks * 16 + cob) * 2u);
#pragma unroll
                for (int mf = 0; mf < 2; mf++) {
                    mma_f16(s[mf][2 * nfp],     qf[mf][ks][0], qf[mf][ks][1],
                            qf[mf][ks][2], qf[mf][ks][3], b0, b1);
                    mma_f16(s[mf][2 * nfp + 1], qf[mf][ks][0], qf[mf][ks][1],
                            qf[mf][ks][2], qf[mf][ks][3], b2, b3);
                }
            }
        }

        // ---- p = 2^s via f16x2 MUFU; half2 row-sum trees; p IS the A-frag ----
        uint32_t ph[2][8][2];
#pragma unroll
        for (int mf = 0; mf < 2; mf++) {
            __half2 sum0 = __float2half2_rn(0.f);
            __half2 sum1 = __float2half2_rn(0.f);
#pragma unroll
            for (int nf = 0; nf < 8; nf++) {
                ph[mf][nf][0] = h2ex2(packh2(s[mf][nf][0], s[mf][nf][1]));
                ph[mf][nf][1] = h2ex2(packh2(s[mf][nf][2], s[mf][nf][3]));
                sum0 = __hadd2(sum0, *(__half2*)&ph[mf][nf][0]);
                sum1 = __hadd2(sum1, *(__half2*)&ph[mf][nf][1]);
            }
            float2 f0 = __half22float2(sum0);
            float2 f1 = __half22float2(sum1);
            lr[mf][0] += f0.x + f0.y;
            lr[mf][1] += f1.x + f1.y;
        }

        // ---- O += P * V ----
        const uint32_t vbase = sb + (uint32_t)((3 + buf) * FA_TILEH) * 2u;
#pragma unroll
        for (int ks = 0; ks < 4; ks++) {
#pragma unroll
            for (int nfp = 0; nfp < 4; nfp++) {
                uint32_t b0, b1, b2, b3;
                ldsm_x4_t(b0, b1, b2, b3,
                          vbase + (uint32_t)((ks * 16 + rv) * HSTR
                                             + nfp * 16 + cv) * 2u);
#pragma unroll
                for (int mf = 0; mf < 2; mf++) {
                    mma_f16(acc_o[mf][2 * nfp],     ph[mf][2 * ks][0], ph[mf][2 * ks][1],
                            ph[mf][2 * ks + 1][0], ph[mf][2 * ks + 1][1], b0, b1);
                    mma_f16(acc_o[mf][2 * nfp + 1], ph[mf][2 * ks][0], ph[mf][2 * ks][1],
                            ph[mf][2 * ks + 1][0], ph[mf][2 * ks + 1][1], b2, b3);
                }
            }
        }
    }

    // ---- epilogue: reduce l across quad once, O / l -> fp16 global ----
#pragma unroll
    for (int mf = 0; mf < 2; mf++) {
        float l0 = lr[mf][0], l1 = lr[mf][1];
        l0 += __shfl_xor_sync(0xFFFFFFFFu, l0, 1);
        l0 += __shfl_xor_sync(0xFFFFFFFFu, l0, 2);
        l1 += __shfl_xor_sync(0xFFFFFFFFu, l1, 1);
        l1 += __shfl_xor_sync(0xFFFFFFFFu, l1, 2);
        const float inv0 = 1.f / l0;
        const float inv1 = 1.f / l1;
        __half* o0 = O + (rowbase + qm0 + m0 + mf * 16 + g) * (size_t)DMODEL
                       + h * DH + 2 * t;
        __half* o1 = o0 + 8 * DMODEL;
#pragma unroll
        for (int nf = 0; nf < 8; nf++) {
            *(uint32_t*)(o0 + nf * 8) =
                packh2(acc_o[mf][nf][0] * inv0, acc_o[mf][nf][1] * inv0);
            *(uint32_t*)(o1 + nf * 8) =
                packh2(acc_o[mf][nf][2] * inv1, acc_o[mf][nf][3] * inv1);
        }
    }
}

// ---------------------------------------------------------------------------
// Launch.
// ---------------------------------------------------------------------------
extern "C" void kernel_launch(void* const* d_in, const int* in_sizes, int n_in,
                              void* d_out, int out_size)
{
    const float* x  = (const float*)d_in[0];
    const float* Wq = (const float*)d_in[1];
    const float* Wk = (const float*)d_in[2];
    const float* Wv = (const float*)d_in[3];
    const float* Wo = (const float*)d_in[4];
    const float* qn = (const float*)d_in[5];
    const float* kn = (const float*)d_in[6];
    float* out = (float*)d_out;

    __half *xh, *wqh, *wkh, *wvh, *woh, *Qh, *Kh, *Vh, *Oh;
    cudaGetSymbolAddress((void**)&xh,  g_xh);
    cudaGetSymbolAddress((void**)&wqh, g_Wqh);
    cudaGetSymbolAddress((void**)&wkh, g_Wkh);
    cudaGetSymbolAddress((void**)&wvh, g_Wvh);
    cudaGetSymbolAddress((void**)&woh, g_Woh);
    cudaGetSymbolAddress((void**)&Qh,  g_Qh);
    cudaGetSymbolAddress((void**)&Kh,  g_Kh);
    cudaGetSymbolAddress((void**)&Vh,  g_Vh);
    cudaGetSymbolAddress((void**)&Oh,  g_Oh);

    cudaFuncSetAttribute(gemm_f16,
                         cudaFuncAttributeMaxDynamicSharedMemorySize, GSM_BYTES);
    cudaFuncSetAttribute(gemm_qkv,
                         cudaFuncAttributeMaxDynamicSharedMemorySize, GSM_BYTES);
    cudaFuncSetAttribute(flash_attn_f16,
                         cudaFuncAttributeMaxDynamicSharedMemorySize, FA_BYTES);

    // fused fp32 -> fp16 conversion (x + 4 weights), MLP=4
    cvt_all<<<CVT_BLOCKS, CVT_TPB>>>((const float4*)x, (const float4*)Wq,
                                     (const float4*)Wk, (const float4*)Wv,
                                     (const float4*)Wo,
                                     (uint2*)xh, (uint2*)wqh, (uint2*)wkh,
                                     (uint2*)wvh, (uint2*)woh);

    // fused QKV projection (R8 config)
    gemm_qkv<<<dim3(24, ROWS / 128), 128, GSM_BYTES>>>(
        xh, wqh, wkh, wvh, Qh, Kh, Vh, qn, kn);

    flash_attn_f16<<<dim3(SEQ / 128, Bq * NH), 128, FA_BYTES>>>(Qh, Kh, Vh, Oh);

    gemm_f16<<<dim3(DMODEL / 128, ROWS / 128), 128, GSM_BYTES>>>(
        Oh, woh, out, nullptr, 0, 0);
}

// round 13
// speedup vs baseline: 1.0901x; 1.0011x over previous
#include <cuda_runtime.h>
#include <cuda_fp16.h>
#include <math.h>
#include <cstdint>

// Problem shape (fixed by the reference).
#define Bq      4
#define SEQ     2048
#define DMODEL  1024
#define NH      16
#define DH      64
#define ROWS    (Bq * SEQ)      // 8192

#define F32_EPS 1.1920929e-07f

// fp16 scratch: device globals (no cudaMalloc allowed).
__device__ __half g_xh[ROWS * DMODEL];
__device__ __half g_Wqh[DMODEL * DMODEL];
__device__ __half g_Wkh[DMODEL * DMODEL];
__device__ __half g_Wvh[DMODEL * DMODEL];
__device__ __half g_Woh[DMODEL * DMODEL];
__device__ __half g_Qh[ROWS * DMODEL];
__device__ __half g_Kh[ROWS * DMODEL];
__device__ __half g_Vh[ROWS * DMODEL];
__device__ __half g_Oh[ROWS * DMODEL];

// ===========================================================================
// Helpers.
// ===========================================================================
__device__ __forceinline__ uint32_t smem_to_u32(const void* p) {
    uint32_t a;
    asm("{ .reg .u64 t; cvta.to.shared.u64 t, %1; cvt.u32.u64 %0, t; }"
        : "=r"(a) : "l"(p));
    return a;
}
__device__ __forceinline__ void mma_f16(float* c, uint32_t a0, uint32_t a1,
                                        uint32_t a2, uint32_t a3,
                                        uint32_t b0, uint32_t b1) {
    asm volatile(
        "mma.sync.aligned.m16n8k16.row.col.f32.f16.f16.f32 "
        "{%0,%1,%2,%3}, {%4,%5,%6,%7}, {%8,%9}, {%0,%1,%2,%3};"
        : "+f"(c[0]), "+f"(c[1]), "+f"(c[2]), "+f"(c[3])
        : "r"(a0), "r"(a1), "r"(a2), "r"(a3), "r"(b0), "r"(b1));
}
__device__ __forceinline__ void ldsm_x4(uint32_t& r0, uint32_t& r1,
                                        uint32_t& r2, uint32_t& r3, uint32_t a) {
    asm volatile("ldmatrix.sync.aligned.m8n8.x4.shared.b16 {%0,%1,%2,%3}, [%4];"
                 : "=r"(r0), "=r"(r1), "=r"(r2), "=r"(r3) : "r"(a));
}
__device__ __forceinline__ void ldsm_x4_t(uint32_t& r0, uint32_t& r1,
                                          uint32_t& r2, uint32_t& r3, uint32_t a) {
    asm volatile("ldmatrix.sync.aligned.m8n8.x4.trans.shared.b16 {%0,%1,%2,%3}, [%4];"
                 : "=r"(r0), "=r"(r1), "=r"(r2), "=r"(r3) : "r"(a));
}
__device__ __forceinline__ void cp_async16(uint32_t dst, const void* src) {
    asm volatile("cp.async.cg.shared.global [%0], [%1], 16;"
                 :: "r"(dst), "l"(src));
}
#define CP_COMMIT() asm volatile("cp.async.commit_group;" ::: "memory")
#define CP_WAIT(n)  asm volatile("cp.async.wait_group %0;" :: "n"(n) : "memory")

__device__ __forceinline__ uint32_t packh2(float x, float y) {
    __half2 h = __floats2half2_rn(x, y);
    return *(uint32_t*)&h;
}
// 2 exponentials (base 2) on a packed half2 in ONE MUFU op.
__device__ __forceinline__ uint32_t h2ex2(uint32_t x) {
    uint32_t r;
    asm("ex2.approx.f16x2 %0, %1;" : "=r"(r) : "r"(x));
    return r;
}

// ===========================================================================
// fp32 -> fp16 conversion, MLP=4 (R12 config).
// ===========================================================================
#define NX4 (ROWS * DMODEL / 4)      // 2097152 float4s in x
#define NW4 (DMODEL * DMODEL / 4)    // 262144 float4s per weight
#define NTOT4 (NX4 + 4 * NW4)        // 3145728
#define CVT_TPB 256
#define CVT_PER_THREAD 4
#define CVT_BLOCKS (NTOT4 / (CVT_TPB * CVT_PER_THREAD))   // 3072

__global__ void __launch_bounds__(CVT_TPB)
cvt_all(const float4* __restrict__ x,
        const float4* __restrict__ w0, const float4* __restrict__ w1,
        const float4* __restrict__ w2, const float4* __restrict__ w3,
        uint2* __restrict__ dx, uint2* __restrict__ dw0,
        uint2* __restrict__ dw1, uint2* __restrict__ dw2,
        uint2* __restrict__ dw3)
{
    const int base = blockIdx.x * (CVT_TPB * CVT_PER_THREAD);
    const float4* s;
    uint2* d;
    int rbase;
    if (base < NX4) {
        s = x; d = dx; rbase = base;
    } else {
        int j = base - NX4;
        int wsel = j >> 18;
        rbase = j & (NW4 - 1);
        s = wsel == 0 ? w0 : wsel == 1 ? w1 : wsel == 2 ? w2 : w3;
        d = wsel == 0 ? dw0 : wsel == 1 ? dw1 : wsel == 2 ? dw2 : dw3;
    }
    float4 v[CVT_PER_THREAD];
#pragma unroll
    for (int i = 0; i < CVT_PER_THREAD; i++)
        v[i] = s[rbase + threadIdx.x + i * CVT_TPB];
#pragma unroll
    for (int i = 0; i < CVT_PER_THREAD; i++)
        d[rbase + threadIdx.x + i * CVT_TPB] =
            make_uint2(packh2(v[i].x, v[i].y), packh2(v[i].z, v[i].w));
}

// ===========================================================================
// fp16 tensor-core GEMM body (NT) — R8/R12-best config (byte-identical).
// ===========================================================================
#define GBK     64
#define GNCH    (DMODEL / GBK)       // 16
#define GASTR   72                   // halves per smem row (144 B)
#define GMATB   (128 * GASTR * 2)    // 18432 bytes per matrix per stage
#define GSTGB   (2 * GMATB)          // 36864 bytes per stage
#define GSM_BYTES (3 * GSTGB)        // 110592

__device__ __forceinline__ void
gemm_body(__half* gsm, const __half* __restrict__ A, const __half* __restrict__ B,
          void* __restrict__ Cv, const float* __restrict__ w,
          int do_rms, int out_half, int bm, int bn)
{
    const uint32_t sb = smem_to_u32(gsm);
    const int tid  = threadIdx.x;
    const int wid  = tid >> 5;
    const int lane = tid & 31;
    const int g    = lane >> 2;
    const int t    = lane & 3;
    const int warpM = wid >> 1;
    const int warpN = wid & 1;

    const int l15 = lane & 15, lq = lane >> 4;
    const int rbl = lq * 8 + (lane & 7);
    const int cob = ((lane >> 3) & 1) * 8;

    const __half* Ag = A + (size_t)bm * DMODEL;
    const __half* Bg = B + (size_t)bn * DMODEL;

    float acc[4][8][4];
#pragma unroll
    for (int i = 0; i < 4; i++)
#pragma unroll
        for (int j = 0; j < 8; j++)
#pragma unroll
            for (int k = 0; k < 4; k++) acc[i][j][k] = 0.f;

    auto load_stage = [&](int chunk, int st) {
        const uint32_t abase = sb + (uint32_t)st * GSTGB;
        const uint32_t bbase = abase + GMATB;
#pragma unroll
        for (int i = 0; i < 8; i++) {
            const int idx = tid + i * 128;
            const int row = idx >> 3;
            const int c8  = idx & 7;
            const uint32_t so = (uint32_t)(row * GASTR + c8 * 8) * 2u;
            const size_t go = (size_t)row * DMODEL + chunk * GBK + c8 * 8;
            cp_async16(abase + so, Ag + go);
            cp_async16(bbase + so, Bg + go);
        }
    };

    load_stage(0, 0); CP_COMMIT();
    load_stage(1, 1); CP_COMMIT();

    for (int i = 0; i < GNCH; i++) {
        const int st = i % 3;
        if (i == GNCH - 1) { CP_WAIT(0); } else { CP_WAIT(1); }
        __syncthreads();
        if (i + 2 < GNCH) { load_stage(i + 2, (i + 2) % 3); CP_COMMIT(); }

        const uint32_t abase = sb + (uint32_t)st * GSTGB;
        const uint32_t bbase = abase + GMATB;
#pragma unroll
        for (int ks = 0; ks < 4; ks++) {
            uint32_t a[4][4];
#pragma unroll
            for (int mf = 0; mf < 4; mf++)
                ldsm_x4(a[mf][0], a[mf][1], a[mf][2], a[mf][3],
                        abase + (uint32_t)((warpM * 64 + mf * 16 + l15) * GASTR
                                           + ks * 16 + lq * 8) * 2u);
#pragma unroll
            for (int nfp = 0; nfp < 4; nfp++) {
                uint32_t b0, b1, b2, b3;
                ldsm_x4(b0, b1, b2, b3,
                        bbase + (uint32_t)((warpN * 64 + nfp * 16 + rbl) * GASTR
                                           + ks * 16 + cob) * 2u);
#pragma unroll
                for (int mf = 0; mf < 4; mf++) {
                    mma_f16(acc[mf][2 * nfp],     a[mf][0], a[mf][1], a[mf][2], a[mf][3], b0, b1);
                    mma_f16(acc[mf][2 * nfp + 1], a[mf][0], a[mf][1], a[mf][2], a[mf][3], b2, b3);
                }
            }
        }
    }

    // ---------------- epilogue --------------------------------------------
#pragma unroll
    for (int mf = 0; mf < 4; mf++) {
        if (do_rms) {
            float ssl = 0.f, ssh = 0.f;
#pragma unroll
            for (int nf = 0; nf < 8; nf++) {
                ssl += acc[mf][nf][0] * acc[mf][nf][0]
                     + acc[mf][nf][1] * acc[mf][nf][1];
                ssh += acc[mf][nf][2] * acc[mf][nf][2]
                     + acc[mf][nf][3] * acc[mf][nf][3];
            }
            ssl += __shfl_xor_sync(0xFFFFFFFFu, ssl, 1);
            ssl += __shfl_xor_sync(0xFFFFFFFFu, ssl, 2);
            ssh += __shfl_xor_sync(0xFFFFFFFFu, ssh, 1);
            ssh += __shfl_xor_sync(0xFFFFFFFFu, ssh, 2);
            const float rl = rsqrtf(ssl * (1.0f / 64.0f) + F32_EPS);
            const float rh = rsqrtf(ssh * (1.0f / 64.0f) + F32_EPS);
#pragma unroll
            for (int nf = 0; nf < 8; nf++) {
                const int hc = nf * 8 + 2 * t;
                const float w0 = w[hc], w1 = w[hc + 1];
                acc[mf][nf][0] *= rl * w0;
                acc[mf][nf][1] *= rl * w1;
                acc[mf][nf][2] *= rh * w0;
                acc[mf][nf][3] *= rh * w1;
            }
        }
        const int r0 = bm + warpM * 64 + mf * 16 + g;
        const int cc = bn + warpN * 64 + 2 * t;
        if (out_half) {
            __half* C = (__half*)Cv;
            uint32_t* c0 = (uint32_t*)(C + (size_t)r0 * DMODEL + cc);
            uint32_t* c1 = (uint32_t*)(C + (size_t)(r0 + 8) * DMODEL + cc);
#pragma unroll
            for (int nf = 0; nf < 8; nf++) {
                c0[nf * 4] = packh2(acc[mf][nf][0], acc[mf][nf][1]);
                c1[nf * 4] = packh2(acc[mf][nf][2], acc[mf][nf][3]);
            }
        } else {
            float* C = (float*)Cv;
            float* c0 = C + (size_t)r0 * DMODEL + cc;
            float* c1 = C + (size_t)(r0 + 8) * DMODEL + cc;
#pragma unroll
            for (int nf = 0; nf < 8; nf++) {
                *(float2*)(c0 + nf * 8) = make_float2(acc[mf][nf][0], acc[mf][nf][1]);
                *(float2*)(c1 + nf * 8) = make_float2(acc[mf][nf][2], acc[mf][nf][3]);
            }
        }
    }
}

// Fused QKV projection (R8 config): grid.x = 24 (matrix = x/8, col tile = x%8).
__global__ void __launch_bounds__(128, 2)
gemm_qkv(const __half* __restrict__ A,
         const __half* __restrict__ Bqm, const __half* __restrict__ Bkm,
         const __half* __restrict__ Bvm,
         __half* __restrict__ Cq, __half* __restrict__ Ck, __half* __restrict__ Cv_,
         const float* __restrict__ qn, const float* __restrict__ kn)
{
    extern __shared__ __half gsm[];
    const int m = blockIdx.x >> 3;
    const int bn = (blockIdx.x & 7) * 128;
    const __half* B = m == 0 ? Bqm : m == 1 ? Bkm : Bvm;
    __half* C = m == 0 ? Cq : m == 1 ? Ck : Cv_;
    const float* w = m == 0 ? qn : m == 1 ? kn : nullptr;
    gemm_body(gsm, A, B, C, w, m < 2 ? 1 : 0, 1, blockIdx.y * 128, bn);
}

// Single GEMM (output projection), fp32 out.
__global__ void __launch_bounds__(128, 2)
gemm_f16(const __half* __restrict__ A, const __half* __restrict__ B,
         void* __restrict__ Cv, const float* __restrict__ w,
         int do_rms, int out_half)
{
    extern __shared__ __half gsm[];
    gemm_body(gsm, A, B, Cv, w, do_rms, out_half,
              blockIdx.y * 128, blockIdx.x * 128);
}

// ===========================================================================
// fp16 flash attention — pair-granular KV pipeline: tiles prefetched in PAIRS
// (128 keys) with a 3-pair ring (6 K + 6 V buffers, 110.6 KB) => ONE
// __syncthreads + ONE cp.async wait per 2 tiles (16 total vs 32).
// Inner 64-key processing identical to R12 (same math, same rel_err).
// 128 threads, 4 warps x 32 q-rows, 2 CTAs/SM (221 KB total smem).
// ===========================================================================
#define HSTR 72                       // halves per smem row (144 B)
#define FA_TILEH (64 * HSTR)          // 4608 halves per KV tile buffer
#define FA_NT (SEQ / 64)              // 32 tiles
#define FA_NP (FA_NT / 2)             // 16 pairs
#define FA_BYTES (12 * FA_TILEH * 2)  // 110592 B (K0..K5, V0..V5)

__global__ void __launch_bounds__(128, 2)
flash_attn_f16(const __half* __restrict__ Q, const __half* __restrict__ K,
               const __half* __restrict__ V, __half* __restrict__ O)
{
    extern __shared__ __half fs[];
    const uint32_t sb = smem_to_u32(fs);
    const int tid  = threadIdx.x;
    const int wid  = tid >> 5;
    const int lane = tid & 31;
    const int g    = lane >> 2;
    const int t    = lane & 3;
    const int bh = blockIdx.y;
    const int b  = bh >> 4;
    const int h  = bh & 15;
    const size_t rowbase = (size_t)b * SEQ;
    const int qm0 = blockIdx.x * 128;
    const int m0  = wid * 32;

    const int l15 = lane & 15, lq = lane >> 4;
    const int rbl = lq * 8 + (lane & 7);             // K ldmatrix row pattern
    const int cob = ((lane >> 3) & 1) * 8;           // K col offset
    const int rv  = ((lane >> 3) & 1) * 8 + (lane & 7);  // V trans row pattern
    const int cv  = lq * 8;                          // V trans col offset

    // ---- stage Q (128 x 64 halves) in buffer region, extract frags ----
    {
        const __half* Qg = Q + (rowbase + qm0) * DMODEL + h * DH;
#pragma unroll
        for (int i = 0; i < 8; i++) {
            const int idx = tid + i * 128;
            const int row = idx >> 3, c8 = idx & 7;
            cp_async16(sb + (uint32_t)(row * HSTR + c8 * 8) * 2u,
                       Qg + (size_t)row * DMODEL + c8 * 8);
        }
        CP_COMMIT(); CP_WAIT(0);
        __syncthreads();
    }
    uint32_t qf[2][4][4];
    // scale = 1/sqrt(64) * log2(e): ex2(s) == exp(q.k / 8)
    const __half2 qsc = __float2half2_rn(0.125f * 1.4426950408889634f);
#pragma unroll
    for (int mf = 0; mf < 2; mf++)
#pragma unroll
        for (int ks = 0; ks < 4; ks++) {
            ldsm_x4(qf[mf][ks][0], qf[mf][ks][1], qf[mf][ks][2], qf[mf][ks][3],
                    sb + (uint32_t)((m0 + mf * 16 + l15) * HSTR
                                    + ks * 16 + lq * 8) * 2u);
#pragma unroll
            for (int j = 0; j < 4; j++) {
                __half2* hp = (__half2*)&qf[mf][ks][j];
                *hp = __hmul2(*hp, qsc);
            }
        }
    __syncthreads();   // Q staging region about to be reused by KV buffers

    float acc_o[2][8][4];
#pragma unroll
    for (int i = 0; i < 2; i++)
#pragma unroll
        for (int j = 0; j < 8; j++)
#pragma unroll
            for (int k = 0; k < 4; k++) acc_o[i][j][k] = 0.f;
    float lr[2][2] = {{0.f, 0.f}, {0.f, 0.f}};

    // tile-buffer tb in 0..5: K at tb*FA_TILEH, V at (6+tb)*FA_TILEH
    auto load_kv = [&](int tile, int tb) {
        const __half* Kg = K + (rowbase + tile * 64) * DMODEL + h * DH;
        const __half* Vg = V + (rowbase + tile * 64) * DMODEL + h * DH;
        const uint32_t kb = sb + (uint32_t)(tb * FA_TILEH) * 2u;
        const uint32_t vb = sb + (uint32_t)((6 + tb) * FA_TILEH) * 2u;
#pragma unroll
        for (int i = 0; i < 4; i++) {
            const int idx = tid + i * 128;
            const int row = idx >> 3, c8 = idx & 7;
            const uint32_t so = (uint32_t)(row * HSTR + c8 * 8) * 2u;
            const size_t go = (size_t)row * DMODEL + c8 * 8;
            cp_async16(kb + so, Kg + go);
            cp_async16(vb + so, Vg + go);
        }
    };
    auto load_pair = [&](int p, int bset) {
        load_kv(2 * p,     2 * bset);
        load_kv(2 * p + 1, 2 * bset + 1);
        CP_COMMIT();
    };

    load_pair(0, 0);
    load_pair(1, 1);

    for (int p = 0; p < FA_NP; p++) {
        const int bset = p % 3;
        if (p + 1 < FA_NP) { CP_WAIT(1); } else { CP_WAIT(0); }
        __syncthreads();   // pair p visible; bufset (p+2)%3 (pair p-1's) free
        if (p + 2 < FA_NP) load_pair(p + 2, (p + 2) % 3);

#pragma unroll
        for (int sub = 0; sub < 2; sub++) {
            const int tb = 2 * bset + sub;

            // ---- S = Q * K^T (log2 units) ----
            float s[2][8][4];
#pragma unroll
            for (int i = 0; i < 2; i++)
#pragma unroll
                for (int j = 0; j < 8; j++)
#pragma unroll
                    for (int k = 0; k < 4; k++) s[i][j][k] = 0.f;

            const uint32_t kbase = sb + (uint32_t)(tb * FA_TILEH) * 2u;
#pragma unroll
            for (int ks = 0; ks < 4; ks++) {
#pragma unroll
                for (int nfp = 0; nfp < 4; nfp++) {
                    uint32_t b0, b1, b2, b3;
                    ldsm_x4(b0, b1, b2, b3,
                            kbase + (uint32_t)((nfp * 16 + rbl) * HSTR
                                               + ks * 16 + cob) * 2u);
#pragma unroll
                    for (int mf = 0; mf < 2; mf++) {
                        mma_f16(s[mf][2 * nfp],     qf[mf][ks][0], qf[mf][ks][1],
                                qf[mf][ks][2], qf[mf][ks][3], b0, b1);
                        mma_f16(s[mf][2 * nfp + 1], qf[mf][ks][0], qf[mf][ks][1],
                                qf[mf][ks][2], qf[mf][ks][3], b2, b3);
                    }
                }
            }

            // ---- p = 2^s via f16x2 MUFU; half2 row sums; p IS the A-frag ----
            uint32_t ph[2][8][2];
#pragma unroll
            for (int mf = 0; mf < 2; mf++) {
                __half2 sum0 = __float2half2_rn(0.f);
                __half2 sum1 = __float2half2_rn(0.f);
#pragma unroll
                for (int nf = 0; nf < 8; nf++) {
                    ph[mf][nf][0] = h2ex2(packh2(s[mf][nf][0], s[mf][nf][1]));
                    ph[mf][nf][1] = h2ex2(packh2(s[mf][nf][2], s[mf][nf][3]));
                    sum0 = __hadd2(sum0, *(__half2*)&ph[mf][nf][0]);
                    sum1 = __hadd2(sum1, *(__half2*)&ph[mf][nf][1]);
                }
                float2 f0 = __half22float2(sum0);
                float2 f1 = __half22float2(sum1);
                lr[mf][0] += f0.x + f0.y;
                lr[mf][1] += f1.x + f1.y;
            }

            // ---- O += P * V ----
            const uint32_t vbase = sb + (uint32_t)((6 + tb) * FA_TILEH) * 2u;
#pragma unroll
            for (int ks = 0; ks < 4; ks++) {
#pragma unroll
                for (int nfp = 0; nfp < 4; nfp++) {
                    uint32_t b0, b1, b2, b3;
                    ldsm_x4_t(b0, b1, b2, b3,
                              vbase + (uint32_t)((ks * 16 + rv) * HSTR
                                                 + nfp * 16 + cv) * 2u);
#pragma unroll
                    for (int mf = 0; mf < 2; mf++) {
                        mma_f16(acc_o[mf][2 * nfp],
                                ph[mf][2 * ks][0], ph[mf][2 * ks][1],
                                ph[mf][2 * ks + 1][0], ph[mf][2 * ks + 1][1],
                                b0, b1);
                        mma_f16(acc_o[mf][2 * nfp + 1],
                                ph[mf][2 * ks][0], ph[mf][2 * ks][1],
                                ph[mf][2 * ks + 1][0], ph[mf][2 * ks + 1][1],
                                b2, b3);
                    }
                }
            }
        }
    }

    // ---- epilogue: reduce l across quad once, O / l -> fp16 global ----
#pragma unroll
    for (int mf = 0; mf < 2; mf++) {
        float l0 = lr[mf][0], l1 = lr[mf][1];
        l0 += __shfl_xor_sync(0xFFFFFFFFu, l0, 1);
        l0 += __shfl_xor_sync(0xFFFFFFFFu, l0, 2);
        l1 += __shfl_xor_sync(0xFFFFFFFFu, l1, 1);
        l1 += __shfl_xor_sync(0xFFFFFFFFu, l1, 2);
        const float inv0 = 1.f / l0;
        const float inv1 = 1.f / l1;
        __half* o0 = O + (rowbase + qm0 + m0 + mf * 16 + g) * (size_t)DMODEL
                       + h * DH + 2 * t;
        __half* o1 = o0 + 8 * DMODEL;
#pragma unroll
        for (int nf = 0; nf < 8; nf++) {
            *(uint32_t*)(o0 + nf * 8) =
                packh2(acc_o[mf][nf][0] * inv0, acc_o[mf][nf][1] * inv0);
            *(uint32_t*)(o1 + nf * 8) =
                packh2(acc_o[mf][nf][2] * inv1, acc_o[mf][nf][3] * inv1);
        }
    }
}

// ---------------------------------------------------------------------------
// Launch.
// ---------------------------------------------------------------------------
extern "C" void kernel_launch(void* const* d_in, const int* in_sizes, int n_in,
                              void* d_out, int out_size)
{
    const float* x  = (const float*)d_in[0];
    const float* Wq = (const float*)d_in[1];
    const float* Wk = (const float*)d_in[2];
    const float* Wv = (const float*)d_in[3];
    const float* Wo = (const float*)d_in[4];
    const float* qn = (const float*)d_in[5];
    const float* kn = (const float*)d_in[6];
    float* out = (float*)d_out;

    __half *xh, *wqh, *wkh, *wvh, *woh, *Qh, *Kh, *Vh, *Oh;
    cudaGetSymbolAddress((void**)&xh,  g_xh);
    cudaGetSymbolAddress((void**)&wqh, g_Wqh);
    cudaGetSymbolAddress((void**)&wkh, g_Wkh);
    cudaGetSymbolAddress((void**)&wvh, g_Wvh);
    cudaGetSymbolAddress((void**)&woh, g_Woh);
    cudaGetSymbolAddress((void**)&Qh,  g_Qh);
    cudaGetSymbolAddress((void**)&Kh,  g_Kh);
    cudaGetSymbolAddress((void**)&Vh,  g_Vh);
    cudaGetSymbolAddress((void**)&Oh,  g_Oh);

    cudaFuncSetAttribute(gemm_f16,
                         cudaFuncAttributeMaxDynamicSharedMemorySize, GSM_BYTES);
    cudaFuncSetAttribute(gemm_qkv,
                         cudaFuncAttributeMaxDynamicSharedMemorySize, GSM_BYTES);
    cudaFuncSetAttribute(flash_attn_f16,
                         cudaFuncAttributeMaxDynamicSharedMemorySize, FA_BYTES);

    // fused fp32 -> fp16 conversion (x + 4 weights), MLP=4
    cvt_all<<<CVT_BLOCKS, CVT_TPB>>>((const float4*)x, (const float4*)Wq,
                                     (const float4*)Wk, (const float4*)Wv,
                                     (const float4*)Wo,
                                     (uint2*)xh, (uint2*)wqh, (uint2*)wkh,
                                     (uint2*)wvh, (uint2*)woh);

    // fused QKV projection (R8 config)
    gemm_qkv<<<dim3(24, ROWS / 128), 128, GSM_BYTES>>>(
        xh, wqh, wkh, wvh, Qh, Kh, Vh, qn, kn);

    flash_attn_f16<<<dim3(SEQ / 128, Bq * NH), 128, FA_BYTES>>>(Qh, Kh, Vh, Oh);

    gemm_f16<<<dim3(DMODEL / 128, ROWS / 128), 128, GSM_BYTES>>>(
        Oh, woh, out, nullptr, 0, 0);
}

// round 15
// speedup vs baseline: 1.1621x; 1.0660x over previous
#include <cuda_runtime.h>
#include <cuda_fp16.h>
#include <math.h>
#include <cstdint>

// Problem shape (fixed by the reference).
#define Bq      4
#define SEQ     2048
#define DMODEL  1024
#define NH      16
#define DH      64
#define ROWS    (Bq * SEQ)      // 8192

#define F32_EPS 1.1920929e-07f

// fp16 scratch: device globals (no cudaMalloc allowed).
__device__ __half g_xh[ROWS * DMODEL];
__device__ __half g_Wqh[DMODEL * DMODEL];
__device__ __half g_Wkh[DMODEL * DMODEL];
__device__ __half g_Wvh[DMODEL * DMODEL];
__device__ __half g_Woh[DMODEL * DMODEL];
__device__ __half g_Qh[ROWS * DMODEL];
__device__ __half g_Kh[ROWS * DMODEL];
__device__ __half g_Vh[ROWS * DMODEL];
__device__ __half g_Oh[ROWS * DMODEL];

// ===========================================================================
// Helpers.
// ===========================================================================
__device__ __forceinline__ uint32_t smem_to_u32(const void* p) {
    uint32_t a;
    asm("{ .reg .u64 t; cvta.to.shared.u64 t, %1; cvt.u32.u64 %0, t; }"
        : "=r"(a) : "l"(p));
    return a;
}
__device__ __forceinline__ void mma_f16(float* c, uint32_t a0, uint32_t a1,
                                        uint32_t a2, uint32_t a3,
                                        uint32_t b0, uint32_t b1) {
    asm volatile(
        "mma.sync.aligned.m16n8k16.row.col.f32.f16.f16.f32 "
        "{%0,%1,%2,%3}, {%4,%5,%6,%7}, {%8,%9}, {%0,%1,%2,%3};"
        : "+f"(c[0]), "+f"(c[1]), "+f"(c[2]), "+f"(c[3])
        : "r"(a0), "r"(a1), "r"(a2), "r"(a3), "r"(b0), "r"(b1));
}
__device__ __forceinline__ void ldsm_x4(uint32_t& r0, uint32_t& r1,
                                        uint32_t& r2, uint32_t& r3, uint32_t a) {
    asm volatile("ldmatrix.sync.aligned.m8n8.x4.shared.b16 {%0,%1,%2,%3}, [%4];"
                 : "=r"(r0), "=r"(r1), "=r"(r2), "=r"(r3) : "r"(a));
}
__device__ __forceinline__ void ldsm_x4_t(uint32_t& r0, uint32_t& r1,
                                          uint32_t& r2, uint32_t& r3, uint32_t a) {
    asm volatile("ldmatrix.sync.aligned.m8n8.x4.trans.shared.b16 {%0,%1,%2,%3}, [%4];"
                 : "=r"(r0), "=r"(r1), "=r"(r2), "=r"(r3) : "r"(a));
}
__device__ __forceinline__ void cp_async16(uint32_t dst, const void* src) {
    asm volatile("cp.async.cg.shared.global [%0], [%1], 16;"
                 :: "r"(dst), "l"(src));
}
#define CP_COMMIT() asm volatile("cp.async.commit_group;" ::: "memory")
#define CP_WAIT(n)  asm volatile("cp.async.wait_group %0;" :: "n"(n) : "memory")

#define MBARRIER_INIT(mbar, count) \
    asm volatile("mbarrier.init.shared.b64 [%0], %1;" \
        :: "r"((uint32_t)(mbar)), "r"((uint32_t)(count)) : "memory")
#define MBARRIER_ARRIVE(mbar) \
    asm volatile("mbarrier.arrive.shared.b64 _, [%0];" \
        :: "r"((uint32_t)(mbar)) : "memory")
// .noinc is LOAD-BEARING: without it the arrive-on increments the expected
// count at issue and consumes its own increment (net zero) => deadlock.
#define CP_ASYNC_MBARRIER_ARRIVE_NOINC(mbar) \
    asm volatile("cp.async.mbarrier.arrive.noinc.shared.b64 [%0];" \
        :: "r"((uint32_t)(mbar)) : "memory")
#define MBARRIER_WAIT_PARITY(mbar_smem_addr, phase_parity) do { \
    uint32_t _mbar = (uint32_t)(mbar_smem_addr); \
    uint32_t _parity = (uint32_t)(phase_parity); \
    uint32_t _done; \
    asm volatile("{\n\t.reg .pred p;\n\t" \
        "mbarrier.try_wait.parity.acquire.cta.shared::cta.b64 p, [%1], %2;\n\t" \
        "selp.b32 %0, 1, 0, p;\n\t}" \
        : "=r"(_done) : "r"(_mbar), "r"(_parity) : "memory"); \
    if (!_done) { \
        asm volatile("{\n\t.reg .pred P1;\n\t" \
            "WAIT_LOOP_%=:\n\t" \
            "mbarrier.try_wait.parity.acquire.cta.shared::cta.b64 P1, [%0], %1, 0x989680;\n\t" \
            "@P1 bra.uni WAIT_DONE_%=;\n\t" \
            "bra.uni WAIT_LOOP_%=;\n\t" \
            "WAIT_DONE_%=:\n\t}" \
            :: "r"(_mbar), "r"(_parity) : "memory"); \
    } \
} while (0)

__device__ __forceinline__ uint32_t packh2(float x, float y) {
    __half2 h = __floats2half2_rn(x, y);
    return *(uint32_t*)&h;
}
__device__ __forceinline__ uint32_t h2ex2(uint32_t x) {
    uint32_t r;
    asm("ex2.approx.f16x2 %0, %1;" : "=r"(r) : "r"(x));
    return r;
}

// ===========================================================================
// fp32 -> fp16 conversion, MLP=4 (R12 config).
// ===========================================================================
#define NX4 (ROWS * DMODEL / 4)
#define NW4 (DMODEL * DMODEL / 4)
#define NTOT4 (NX4 + 4 * NW4)
#define CVT_TPB 256
#define CVT_PER_THREAD 4
#define CVT_BLOCKS (NTOT4 / (CVT_TPB * CVT_PER_THREAD))

__global__ void __launch_bounds__(CVT_TPB)
cvt_all(const float4* __restrict__ x,
        const float4* __restrict__ w0, const float4* __restrict__ w1,
        const float4* __restrict__ w2, const float4* __restrict__ w3,
        uint2* __restrict__ dx, uint2* __restrict__ dw0,
        uint2* __restrict__ dw1, uint2* __restrict__ dw2,
        uint2* __restrict__ dw3)
{
    const int base = blockIdx.x * (CVT_TPB * CVT_PER_THREAD);
    const float4* s;
    uint2* d;
    int rbase;
    if (base < NX4) {
        s = x; d = dx; rbase = base;
    } else {
        int j = base - NX4;
        int wsel = j >> 18;
        rbase = j & (NW4 - 1);
        s = wsel == 0 ? w0 : wsel == 1 ? w1 : wsel == 2 ? w2 : w3;
        d = wsel == 0 ? dw0 : wsel == 1 ? dw1 : wsel == 2 ? dw2 : dw3;
    }
    float4 v[CVT_PER_THREAD];
#pragma unroll
    for (int i = 0; i < CVT_PER_THREAD; i++)
        v[i] = s[rbase + threadIdx.x + i * CVT_TPB];
#pragma unroll
    for (int i = 0; i < CVT_PER_THREAD; i++)
        d[rbase + threadIdx.x + i * CVT_TPB] =
            make_uint2(packh2(v[i].x, v[i].y), packh2(v[i].z, v[i].w));
}

// ===========================================================================
// WARP-SPECIALIZED fp16 GEMM (NT): C[M,N] = A[M,K]*B[N,K]^T, fp32 accum.
// CTA 128x128, BK=64, 3-stage mbarrier ring, 160 threads:
//   warps 0-3: consumers (2Mx2N, warp tile 64x64) — ldsm+MMA ONLY.
//   warp 4:    producer — issues all cp.async; .noinc arrive-on full[s].
// NO __syncthreads in the mainloop.
// ===========================================================================
#define GBK     64
#define GNCH    (DMODEL / GBK)       // 16
#define GASTR   72                   // halves per smem row (144 B)
#define GMATB   (128 * GASTR * 2)    // 18432 bytes per matrix per stage
#define GSTGB   (2 * GMATB)          // 36864 bytes per stage
#define GMB_OFF (3 * GSTGB)          // mbarrier area offset (110592)
#define GSM_BYTES (GMB_OFF + 64)     // 110656

__device__ __forceinline__ void
gemm_body(__half* gsm, const __half* __restrict__ A, const __half* __restrict__ B,
          void* __restrict__ Cv, const float* __restrict__ w,
          int do_rms, int out_half, int bm, int bn)
{
    const uint32_t sb = smem_to_u32(gsm);
    const uint32_t mb = sb + GMB_OFF;      // full[s]=mb+s*16, empty[s]=+8
    const int tid  = threadIdx.x;
    const int wid  = tid >> 5;
    const int lane = tid & 31;

    if (tid == 0) {
#pragma unroll
        for (int s = 0; s < 3; s++) {
            MBARRIER_INIT(mb + s * 16, 32);        // full: 32 producer arrive-ons
            MBARRIER_INIT(mb + s * 16 + 8, 128);   // empty: 128 consumer threads
        }
    }
    __syncthreads();

    if (wid == 4) {
        // ---------------- producer ----------------
        const __half* Ag = A + (size_t)bm * DMODEL;
        const __half* Bg = B + (size_t)bn * DMODEL;
        for (int i = 0; i < GNCH; i++) {
            const int s = i % 3;
            const int c = i / 3;
            if (c > 0) MBARRIER_WAIT_PARITY(mb + s * 16 + 8, (c - 1) & 1);
            const uint32_t abase = sb + (uint32_t)s * GSTGB;
            const uint32_t bbase = abase + GMATB;
            const int kofs = i * GBK;
#pragma unroll
            for (int j = 0; j < 32; j++) {
                const int slot = lane + j * 32;     // 0..1023
                const int row = slot >> 3;
                const int c8  = slot & 7;
                const uint32_t so = (uint32_t)(row * GASTR + c8 * 8) * 2u;
                const size_t go = (size_t)row * DMODEL + kofs + c8 * 8;
                cp_async16(abase + so, Ag + go);
                cp_async16(bbase + so, Bg + go);
            }
            CP_ASYNC_MBARRIER_ARRIVE_NOINC(mb + s * 16);
        }
        return;   // producer done
    }

    // ---------------- consumers (warps 0-3) ----------------
    const int g    = lane >> 2;
    const int t    = lane & 3;
    const int warpM = wid >> 1;
    const int warpN = wid & 1;
    const int l15 = lane & 15, lq = lane >> 4;
    const int rbl = lq * 8 + (lane & 7);
    const int cob = ((lane >> 3) & 1) * 8;

    float acc[4][8][4];
#pragma unroll
    for (int i = 0; i < 4; i++)
#pragma unroll
        for (int j = 0; j < 8; j++)
#pragma unroll
            for (int k = 0; k < 4; k++) acc[i][j][k] = 0.f;

    for (int i = 0; i < GNCH; i++) {
        const int s = i % 3;
        const int c = i / 3;
        MBARRIER_WAIT_PARITY(mb + s * 16, c & 1);

        const uint32_t abase = sb + (uint32_t)s * GSTGB;
        const uint32_t bbase = abase + GMATB;
#pragma unroll
        for (int ks = 0; ks < 4; ks++) {
            uint32_t a[4][4];
#pragma unroll
            for (int mf = 0; mf < 4; mf++)
                ldsm_x4(a[mf][0], a[mf][1], a[mf][2], a[mf][3],
                        abase + (uint32_t)((warpM * 64 + mf * 16 + l15) * GASTR
                                           + ks * 16 + lq * 8) * 2u);
#pragma unroll
            for (int nfp = 0; nfp < 4; nfp++) {
                uint32_t b0, b1, b2, b3;
                ldsm_x4(b0, b1, b2, b3,
                        bbase + (uint32_t)((warpN * 64 + nfp * 16 + rbl) * GASTR
                                           + ks * 16 + cob) * 2u);
#pragma unroll
                for (int mf = 0; mf < 4; mf++) {
                    mma_f16(acc[mf][2 * nfp],     a[mf][0], a[mf][1], a[mf][2], a[mf][3], b0, b1);
                    mma_f16(acc[mf][2 * nfp + 1], a[mf][0], a[mf][1], a[mf][2], a[mf][3], b2, b3);
                }
            }
        }
        MBARRIER_ARRIVE(mb + s * 16 + 8);
    }

    // ---------------- epilogue --------------------------------------------
#pragma unroll
    for (int mf = 0; mf < 4; mf++) {
        if (do_rms) {
            float ssl = 0.f, ssh = 0.f;
#pragma unroll
            for (int nf = 0; nf < 8; nf++) {
                ssl += acc[mf][nf][0] * acc[mf][nf][0]
                     + acc[mf][nf][1] * acc[mf][nf][1];
                ssh += acc[mf][nf][2] * acc[mf][nf][2]
                     + acc[mf][nf][3] * acc[mf][nf][3];
            }
            ssl += __shfl_xor_sync(0xFFFFFFFFu, ssl, 1);
            ssl += __shfl_xor_sync(0xFFFFFFFFu, ssl, 2);
            ssh += __shfl_xor_sync(0xFFFFFFFFu, ssh, 1);
            ssh += __shfl_xor_sync(0xFFFFFFFFu, ssh, 2);
            const float rl = rsqrtf(ssl * (1.0f / 64.0f) + F32_EPS);
            const float rh = rsqrtf(ssh * (1.0f / 64.0f) + F32_EPS);
#pragma unroll
            for (int nf = 0; nf < 8; nf++) {
                const int hc = nf * 8 + 2 * t;
                const float w0 = w[hc], w1 = w[hc + 1];
                acc[mf][nf][0] *= rl * w0;
                acc[mf][nf][1] *= rl * w1;
                acc[mf][nf][2] *= rh * w0;
                acc[mf][nf][3] *= rh * w1;
            }
        }
        const int r0 = bm + warpM * 64 + mf * 16 + g;
        const int cc = bn + warpN * 64 + 2 * t;
        if (out_half) {
            __half* C = (__half*)Cv;
            uint32_t* c0 = (uint32_t*)(C + (size_t)r0 * DMODEL + cc);
            uint32_t* c1 = (uint32_t*)(C + (size_t)(r0 + 8) * DMODEL + cc);
#pragma unroll
            for (int nf = 0; nf < 8; nf++) {
                c0[nf * 4] = packh2(acc[mf][nf][0], acc[mf][nf][1]);
                c1[nf * 4] = packh2(acc[mf][nf][2], acc[mf][nf][3]);
            }
        } else {
            float* C = (float*)Cv;
            float* c0 = C + (size_t)r0 * DMODEL + cc;
            float* c1 = C + (size_t)(r0 + 8) * DMODEL + cc;
#pragma unroll
            for (int nf = 0; nf < 8; nf++) {
                *(float2*)(c0 + nf * 8) = make_float2(acc[mf][nf][0], acc[mf][nf][1]);
                *(float2*)(c1 + nf * 8) = make_float2(acc[mf][nf][2], acc[mf][nf][3]);
            }
        }
    }
}

// Fused QKV projection: grid.x = 24 (matrix = x/8, col tile = x%8).
__global__ void __launch_bounds__(160, 2)
gemm_qkv(const __half* __restrict__ A,
         const __half* __restrict__ Bqm, const __half* __restrict__ Bkm,
         const __half* __restrict__ Bvm,
         __half* __restrict__ Cq, __half* __restrict__ Ck, __half* __restrict__ Cv_,
         const float* __restrict__ qn, const float* __restrict__ kn)
{
    extern __shared__ __half gsm[];
    const int m = blockIdx.x >> 3;
    const int bn = (blockIdx.x & 7) * 128;
    const __half* B = m == 0 ? Bqm : m == 1 ? Bkm : Bvm;
    __half* C = m == 0 ? Cq : m == 1 ? Ck : Cv_;
    const float* w = m == 0 ? qn : m == 1 ? kn : nullptr;
    gemm_body(gsm, A, B, C, w, m < 2 ? 1 : 0, 1, blockIdx.y * 128, bn);
}

// Single GEMM (output projection), fp32 out.
__global__ void __launch_bounds__(160, 2)
gemm_f16(const __half* __restrict__ A, const __half* __restrict__ B,
         void* __restrict__ Cv, const float* __restrict__ w,
         int do_rms, int out_half)
{
    extern __shared__ __half gsm[];
    gemm_body(gsm, A, B, Cv, w, do_rms, out_half,
              blockIdx.y * 128, blockIdx.x * 128);
}

// ===========================================================================
// fp16 flash attention — R13 config (byte-identical): pair-granular KV ring.
// ===========================================================================
#define HSTR 72
#define FA_TILEH (64 * HSTR)
#define FA_NT (SEQ / 64)
#define FA_NP (FA_NT / 2)
#define FA_BYTES (12 * FA_TILEH * 2)   // 110592

__global__ void __launch_bounds__(128, 2)
flash_attn_f16(const __half* __restrict__ Q, const __half* __restrict__ K,
               const __half* __restrict__ V, __half* __restrict__ O)
{
    extern __shared__ __half fs[];
    const uint32_t sb = smem_to_u32(fs);
    const int tid  = threadIdx.x;
    const int wid  = tid >> 5;
    const int lane = tid & 31;
    const int g    = lane >> 2;
    const int t    = lane & 3;
    const int bh = blockIdx.y;
    const int b  = bh >> 4;
    const int h  = bh & 15;
    const size_t rowbase = (size_t)b * SEQ;
    const int qm0 = blockIdx.x * 128;
    const int m0  = wid * 32;

    const int l15 = lane & 15, lq = lane >> 4;
    const int rbl = lq * 8 + (lane & 7);
    const int cob = ((lane >> 3) & 1) * 8;
    const int rv  = ((lane >> 3) & 1) * 8 + (lane & 7);
    const int cv  = lq * 8;

    {
        const __half* Qg = Q + (rowbase + qm0) * DMODEL + h * DH;
#pragma unroll
        for (int i = 0; i < 8; i++) {
            const int idx = tid + i * 128;
            const int row = idx >> 3, c8 = idx & 7;
            cp_async16(sb + (uint32_t)(row * HSTR + c8 * 8) * 2u,
                       Qg + (size_t)row * DMODEL + c8 * 8);
        }
        CP_COMMIT(); CP_WAIT(0);
        __syncthreads();
    }
    uint32_t qf[2][4][4];
    const __half2 qsc = __float2half2_rn(0.125f * 1.4426950408889634f);
#pragma unroll
    for (int mf = 0; mf < 2; mf++)
#pragma unroll
        for (int ks = 0; ks < 4; ks++) {
            ldsm_x4(qf[mf][ks][0], qf[mf][ks][1], qf[mf][ks][2], qf[mf][ks][3],
                    sb + (uint32_t)((m0 + mf * 16 + l15) * HSTR
                                    + ks * 16 + lq * 8) * 2u);
#pragma unroll
            for (int j = 0; j < 4; j++) {
                __half2* hp = (__half2*)&qf[mf][ks][j];
                *hp = __hmul2(*hp, qsc);
            }
        }
    __syncthreads();

    float acc_o[2][8][4];
#pragma unroll
    for (int i = 0; i < 2; i++)
#pragma unroll
        for (int j = 0; j < 8; j++)
#pragma unroll
            for (int k = 0; k < 4; k++) acc_o[i][j][k] = 0.f;
    float lr[2][2] = {{0.f, 0.f}, {0.f, 0.f}};

    auto load_kv = [&](int tile, int tb) {
        const __half* Kg = K + (rowbase + tile * 64) * DMODEL + h * DH;
        const __half* Vg = V + (rowbase + tile * 64) * DMODEL + h * DH;
        const uint32_t kb = sb + (uint32_t)(tb * FA_TILEH) * 2u;
        const uint32_t vb = sb + (uint32_t)((6 + tb) * FA_TILEH) * 2u;
#pragma unroll
        for (int i = 0; i < 4; i++) {
            const int idx = tid + i * 128;
            const int row = idx >> 3, c8 = idx & 7;
            const uint32_t so = (uint32_t)(row * HSTR + c8 * 8) * 2u;
            const size_t go = (size_t)row * DMODEL + c8 * 8;
            cp_async16(kb + so, Kg + go);
            cp_async16(vb + so, Vg + go);
        }
    };
    auto load_pair = [&](int p, int bset) {
        load_kv(2 * p,     2 * bset);
        load_kv(2 * p + 1, 2 * bset + 1);
        CP_COMMIT();
    };

    load_pair(0, 0);
    load_pair(1, 1);

    for (int p = 0; p < FA_NP; p++) {
        const int bset = p % 3;
        if (p + 1 < FA_NP) { CP_WAIT(1); } else { CP_WAIT(0); }
        __syncthreads();
        if (p + 2 < FA_NP) load_pair(p + 2, (p + 2) % 3);

#pragma unroll
        for (int sub = 0; sub < 2; sub++) {
            const int tb = 2 * bset + sub;

            float s[2][8][4];
#pragma unroll
            for (int i = 0; i < 2; i++)
#pragma unroll
                for (int j = 0; j < 8; j++)
#pragma unroll
                    for (int k = 0; k < 4; k++) s[i][j][k] = 0.f;

            const uint32_t kbase = sb + (uint32_t)(tb * FA_TILEH) * 2u;
#pragma unroll
            for (int ks = 0; ks < 4; ks++) {
#pragma unroll
                for (int nfp = 0; nfp < 4; nfp++) {
                    uint32_t b0, b1, b2, b3;
                    ldsm_x4(b0, b1, b2, b3,
                            kbase + (uint32_t)((nfp * 16 + rbl) * HSTR
                                               + ks * 16 + cob) * 2u);
#pragma unroll
                    for (int mf = 0; mf < 2; mf++) {
                        mma_f16(s[mf][2 * nfp],     qf[mf][ks][0], qf[mf][ks][1],
                                qf[mf][ks][2], qf[mf][ks][3], b0, b1);
                        mma_f16(s[mf][2 * nfp + 1], qf[mf][ks][0], qf[mf][ks][1],
                                qf[mf][ks][2], qf[mf][ks][3], b2, b3);
                    }
                }
            }

            uint32_t ph[2][8][2];
#pragma unroll
            for (int mf = 0; mf < 2; mf++) {
                __half2 sum0 = __float2half2_rn(0.f);
                __half2 sum1 = __float2half2_rn(0.f);
#pragma unroll
                for (int nf = 0; nf < 8; nf++) {
                    ph[mf][nf][0] = h2ex2(packh2(s[mf][nf][0], s[mf][nf][1]));
                    ph[mf][nf][1] = h2ex2(packh2(s[mf][nf][2], s[mf][nf][3]));
                    sum0 = __hadd2(sum0, *(__half2*)&ph[mf][nf][0]);
                    sum1 = __hadd2(sum1, *(__half2*)&ph[mf][nf][1]);
                }
                float2 f0 = __half22float2(sum0);
                float2 f1 = __half22float2(sum1);
                lr[mf][0] += f0.x + f0.y;
                lr[mf][1] += f1.x + f1.y;
            }

            const uint32_t vbase = sb + (uint32_t)((6 + tb) * FA_TILEH) * 2u;
#pragma unroll
            for (int ks = 0; ks < 4; ks++) {
#pragma unroll
                for (int nfp = 0; nfp < 4; nfp++) {
                    uint32_t b0, b1, b2, b3;
                    ldsm_x4_t(b0, b1, b2, b3,
                              vbase + (uint32_t)((ks * 16 + rv) * HSTR
                                                 + nfp * 16 + cv) * 2u);
#pragma unroll
                    for (int mf = 0; mf < 2; mf++) {
                        mma_f16(acc_o[mf][2 * nfp],
                                ph[mf][2 * ks][0], ph[mf][2 * ks][1],
                                ph[mf][2 * ks + 1][0], ph[mf][2 * ks + 1][1],
                                b0, b1);
                        mma_f16(acc_o[mf][2 * nfp + 1],
                                ph[mf][2 * ks][0], ph[mf][2 * ks][1],
                                ph[mf][2 * ks + 1][0], ph[mf][2 * ks + 1][1],
                                b2, b3);
                    }
                }
            }
        }
    }

#pragma unroll
    for (int mf = 0; mf < 2; mf++) {
        float l0 = lr[mf][0], l1 = lr[mf][1];
        l0 += __shfl_xor_sync(0xFFFFFFFFu, l0, 1);
        l0 += __shfl_xor_sync(0xFFFFFFFFu, l0, 2);
        l1 += __shfl_xor_sync(0xFFFFFFFFu, l1, 1);
        l1 += __shfl_xor_sync(0xFFFFFFFFu, l1, 2);
        const float inv0 = 1.f / l0;
        const float inv1 = 1.f / l1;
        __half* o0 = O + (rowbase + qm0 + m0 + mf * 16 + g) * (size_t)DMODEL
                       + h * DH + 2 * t;
        __half* o1 = o0 + 8 * DMODEL;
#pragma unroll
        for (int nf = 0; nf < 8; nf++) {
            *(uint32_t*)(o0 + nf * 8) =
                packh2(acc_o[mf][nf][0] * inv0, acc_o[mf][nf][1] * inv0);
            *(uint32_t*)(o1 + nf * 8) =
                packh2(acc_o[mf][nf][2] * inv1, acc_o[mf][nf][3] * inv1);
        }
    }
}

// ---------------------------------------------------------------------------
// Launch.
// ---------------------------------------------------------------------------
extern "C" void kernel_launch(void* const* d_in, const int* in_sizes, int n_in,
                              void* d_out, int out_size)
{
    const float* x  = (const float*)d_in[0];
    const float* Wq = (const float*)d_in[1];
    const float* Wk = (const float*)d_in[2];
    const float* Wv = (const float*)d_in[3];
    const float* Wo = (const float*)d_in[4];
    const float* qn = (const float*)d_in[5];
    const float* kn = (const float*)d_in[6];
    float* out = (float*)d_out;

    __half *xh, *wqh, *wkh, *wvh, *woh, *Qh, *Kh, *Vh, *Oh;
    cudaGetSymbolAddress((void**)&xh,  g_xh);
    cudaGetSymbolAddress((void**)&wqh, g_Wqh);
    cudaGetSymbolAddress((void**)&wkh, g_Wkh);
    cudaGetSymbolAddress((void**)&wvh, g_Wvh);
    cudaGetSymbolAddress((void**)&woh, g_Woh);
    cudaGetSymbolAddress((void**)&Qh,  g_Qh);
    cudaGetSymbolAddress((void**)&Kh,  g_Kh);
    cudaGetSymbolAddress((void**)&Vh,  g_Vh);
    cudaGetSymbolAddress((void**)&Oh,  g_Oh);

    cudaFuncSetAttribute(gemm_f16,
                         cudaFuncAttributeMaxDynamicSharedMemorySize, GSM_BYTES);
    cudaFuncSetAttribute(gemm_qkv,
                         cudaFuncAttributeMaxDynamicSharedMemorySize, GSM_BYTES);
    cudaFuncSetAttribute(flash_attn_f16,
                         cudaFuncAttributeMaxDynamicSharedMemorySize, FA_BYTES);

    cvt_all<<<CVT_BLOCKS, CVT_TPB>>>((const float4*)x, (const float4*)Wq,
                                     (const float4*)Wk, (const float4*)Wv,
                                     (const float4*)Wo,
                                     (uint2*)xh, (uint2*)wqh, (uint2*)wkh,
                                     (uint2*)wvh, (uint2*)woh);

    gemm_qkv<<<dim3(24, ROWS / 128), 160, GSM_BYTES>>>(
        xh, wqh, wkh, wvh, Qh, Kh, Vh, qn, kn);

    flash_attn_f16<<<dim3(SEQ / 128, Bq * NH), 128, FA_BYTES>>>(Qh, Kh, Vh, Oh);

    gemm_f16<<<dim3(DMODEL / 128, ROWS / 128), 160, GSM_BYTES>>>(
        Oh, woh, out, nullptr, 0, 0);
}